// round 2
// baseline (speedup 1.0000x reference)
#include <cuda_runtime.h>
#include <math.h>

#define NTOK   32768
#define C_DIM  384
#define E_NUM  8
#define DFF    1536
#define CAP    8192
#define TM     128
#define TN     128
#define TK     16

// ---------- persistent device scratch (no allocations allowed) ----------
__device__ int   g_texp[NTOK];                       // per-token top-1 expert
__device__ float g_tgate[NTOK];                      // per-token gate weight
__device__ int   g_tok[E_NUM * CAP];                 // per-expert token list (token order)
__device__ float g_gslot[E_NUM * CAP];               // gate per slot
__device__ int   g_count[E_NUM];                     // clamped counts
__device__ int   g_base[E_NUM];                      // exclusive scan of clamped counts
__device__ float g_h[(size_t)(NTOK + TM) * DFF];     // H scratch (~202 MB), padded rows

// ---------------------------- zero output ----------------------------
__global__ __launch_bounds__(256) void kzero(float4* __restrict__ out, int n4) {
    int i = blockIdx.x * blockDim.x + threadIdx.x;
    if (i < n4) out[i] = make_float4(0.f, 0.f, 0.f, 0.f);
}

// ---------------------------- routing ----------------------------
// One warp per token. w_route/w_noise cached in smem transposed [e][c].
__global__ __launch_bounds__(256) void kroute(
        const float* __restrict__ x, const float* __restrict__ noise,
        const float* __restrict__ w_route, const float* __restrict__ b_route,
        const float* __restrict__ w_noise, const float* __restrict__ b_noise) {
    __shared__ float swr[E_NUM * C_DIM];
    __shared__ float swn[E_NUM * C_DIM];
    for (int i = threadIdx.x; i < E_NUM * C_DIM; i += blockDim.x) {
        int c = i >> 3, e = i & 7;
        swr[e * C_DIM + c] = w_route[i];
        swn[e * C_DIM + c] = w_noise[i];
    }
    __syncthreads();

    const int lane = threadIdx.x & 31;
    const int warp = threadIdx.x >> 5;
    const int t = blockIdx.x * 8 + warp;

    float ar[E_NUM], an[E_NUM];
#pragma unroll
    for (int e = 0; e < E_NUM; e++) { ar[e] = 0.f; an[e] = 0.f; }

    const float* xr = x + (size_t)t * C_DIM;
#pragma unroll
    for (int j = 0; j < C_DIM / 32; j++) {
        const int c = j * 32 + lane;
        const float xv = xr[c];
#pragma unroll
        for (int e = 0; e < E_NUM; e++) {
            ar[e] = fmaf(xv, swr[e * C_DIM + c], ar[e]);
            an[e] = fmaf(xv, swn[e * C_DIM + c], an[e]);
        }
    }
#pragma unroll
    for (int e = 0; e < E_NUM; e++) {
#pragma unroll
        for (int off = 16; off > 0; off >>= 1) {
            ar[e] += __shfl_xor_sync(0xffffffffu, ar[e], off);
            an[e] += __shfl_xor_sync(0xffffffffu, an[e], off);
        }
    }
    if (lane == 0) {
        float ns[E_NUM];
        float best = -INFINITY; int bi = 0;
#pragma unroll
        for (int e = 0; e < E_NUM; e++) {
            float lg = ar[e] + b_route[e];
            float z  = an[e] + b_noise[e];
            float sp = fmaxf(z, 0.f) + log1pf(expf(-fabsf(z)));   // stable softplus
            ns[e] = lg + noise[(size_t)t * E_NUM + e] * sp;
            if (ns[e] > best) { best = ns[e]; bi = e; }           // earliest-max (matches argmax)
        }
        float second = -INFINITY;
#pragma unroll
        for (int e = 0; e < E_NUM; e++)
            if (e != bi && ns[e] > second) second = ns[e];
        g_texp[t]  = bi;
        g_tgate[t] = 1.f / (1.f + expf(second - best));           // softmax over top-2
    }
}

// ------------------ ordered compaction (single block, 256 thr) ------------------
// Each thread owns a contiguous 128-token chunk. Two passes over g_texp
// (count, then emit) instead of caching ids in registers — keeps regs*threads
// within launch limits. Exclusive prefix per expert preserves token order.
__global__ __launch_bounds__(256) void kscatter() {
    __shared__ int s[E_NUM][256];
    __shared__ int stot[E_NUM];
    const int tid = threadIdx.x;
    const int CH  = NTOK / 256;   // 128
    const int t0  = tid * CH;

    int cnt[E_NUM];
#pragma unroll
    for (int e = 0; e < E_NUM; e++) cnt[e] = 0;
    for (int i = 0; i < CH; i++) cnt[g_texp[t0 + i]]++;

#pragma unroll
    for (int e = 0; e < E_NUM; e++) s[e][tid] = cnt[e];
    __syncthreads();

    // Hillis-Steele inclusive scan per expert over 256 threads
    for (int off = 1; off < 256; off <<= 1) {
        int v[E_NUM];
#pragma unroll
        for (int e = 0; e < E_NUM; e++) v[e] = (tid >= off) ? s[e][tid - off] : 0;
        __syncthreads();
#pragma unroll
        for (int e = 0; e < E_NUM; e++) s[e][tid] += v[e];
        __syncthreads();
    }

    int run[E_NUM];
#pragma unroll
    for (int e = 0; e < E_NUM; e++) run[e] = s[e][tid] - cnt[e];  // exclusive prefix

    if (tid < E_NUM) stot[tid] = s[tid][255];
    __syncthreads();
    if (tid == 0) {
        int b = 0;
        for (int e = 0; e < E_NUM; e++) {
            int c = stot[e] < CAP ? stot[e] : CAP;
            g_count[e] = c;
            g_base[e]  = b;
            b += c;
        }
    }

    for (int i = 0; i < CH; i++) {
        int t = t0 + i;
        int e = g_texp[t];
        int p = run[e]++;
        if (p < CAP) {
            g_tok[e * CAP + p]   = t;
            g_gslot[e * CAP + p] = g_tgate[t];
        }
    }
}

// ---------------------------- GEMM helpers ----------------------------
#define G_STORE(BUF)                                                              \
    As[BUF][kA + 0][mA] = aR0.x; As[BUF][kA + 1][mA] = aR0.y;                     \
    As[BUF][kA + 2][mA] = aR0.z; As[BUF][kA + 3][mA] = aR0.w;                     \
    As[BUF][kA + 8][mA] = aR1.x; As[BUF][kA + 9][mA] = aR1.y;                     \
    As[BUF][kA +10][mA] = aR1.z; As[BUF][kA +11][mA] = aR1.w;                     \
    *(float4*)&Bs[BUF][kB][nB]     = bR0;                                         \
    *(float4*)&Bs[BUF][kB + 8][nB] = bR1;

#define G_COMPUTE(CUR)                                                            \
    _Pragma("unroll")                                                             \
    for (int k = 0; k < TK; k++) {                                                \
        const float4 a0 = *(const float4*)&As[CUR][k][ty4];                       \
        const float4 a1 = *(const float4*)&As[CUR][k][64 + ty4];                  \
        const float4 b0 = *(const float4*)&Bs[CUR][k][tx4];                       \
        const float4 b1f = *(const float4*)&Bs[CUR][k][64 + tx4];                 \
        float av[8] = {a0.x, a0.y, a0.z, a0.w, a1.x, a1.y, a1.z, a1.w};           \
        float bv[8] = {b0.x, b0.y, b0.z, b0.w, b1f.x, b1f.y, b1f.z, b1f.w};       \
        _Pragma("unroll")                                                         \
        for (int ii = 0; ii < 8; ii++)                                            \
            _Pragma("unroll")                                                     \
            for (int jj = 0; jj < 8; jj++)                                        \
                acc[ii][jj] = fmaf(av[ii], bv[jj], acc[ii][jj]);                  \
    }

// ----------------- GEMM1: H = relu(Xg @ W1 + b1)^2 -----------------
__global__ __launch_bounds__(256, 2) void kgemm1(
    const float* __restrict__ x, const float* __restrict__ w1, const float* __restrict__ b1) {
    const int e  = blockIdx.z;
    const int cnt = g_count[e];
    const int m0 = blockIdx.y * TM;
    if (m0 >= cnt) return;
    const int n0 = blockIdx.x * TN;

    __shared__ float As[2][TK][TM];
    __shared__ float Bs[2][TK][TN];

    const int tid = threadIdx.x;
    const int mA  = tid & 127;
    const int kA  = (tid >> 7) * 4;       // 0 or 4
    const int nB  = (tid & 31) * 4;
    const int kB  = tid >> 5;             // 0..7
    const int tx4 = (tid & 15) * 4;
    const int ty4 = ((tid >> 4) & 15) * 4;

    const int tokA = g_tok[e * CAP + m0 + mA];     // gather (clamped rows read stale — never stored)
    const float* arow = x + (size_t)tokA * C_DIM;
    const float* bcol = w1 + (size_t)e * C_DIM * DFF + n0 + nB;

    float acc[8][8];
#pragma unroll
    for (int ii = 0; ii < 8; ii++)
#pragma unroll
        for (int jj = 0; jj < 8; jj++) acc[ii][jj] = 0.f;

    float4 aR0, aR1, bR0, bR1;

#define G1_LOAD(K0)                                                    \
    aR0 = *(const float4*)(arow + (K0) + kA);                          \
    aR1 = *(const float4*)(arow + (K0) + kA + 8);                      \
    bR0 = *(const float4*)(bcol + (size_t)((K0) + kB) * DFF);          \
    bR1 = *(const float4*)(bcol + (size_t)((K0) + kB + 8) * DFF);

    G1_LOAD(0); G_STORE(0);
    __syncthreads();
    const int NK = C_DIM / TK;  // 24
    for (int kc = 0; kc < NK; kc++) {
        const int cur = kc & 1;
        if (kc + 1 < NK) { G1_LOAD((kc + 1) * TK); }
        G_COMPUTE(cur);
        if (kc + 1 < NK) { const int nxt = cur ^ 1; G_STORE(nxt); }
        __syncthreads();
    }

    const int base = g_base[e];
    const float* b1p = b1 + (size_t)e * DFF + n0;
#pragma unroll
    for (int ih = 0; ih < 2; ih++) {
#pragma unroll
        for (int i = 0; i < 4; i++) {
            const int r = ih * 64 + ty4 + i;
            const int p = m0 + r;
            if (p < cnt) {
                float* gh = g_h + (size_t)(base + p) * DFF + n0;
#pragma unroll
                for (int jh = 0; jh < 2; jh++) {
                    const int c = jh * 64 + tx4;
                    float4 v;
                    float t0 = acc[ih*4+i][jh*4+0] + b1p[c+0]; t0 = fmaxf(t0, 0.f); v.x = t0*t0;
                    float t1 = acc[ih*4+i][jh*4+1] + b1p[c+1]; t1 = fmaxf(t1, 0.f); v.y = t1*t1;
                    float t2 = acc[ih*4+i][jh*4+2] + b1p[c+2]; t2 = fmaxf(t2, 0.f); v.z = t2*t2;
                    float t3 = acc[ih*4+i][jh*4+3] + b1p[c+3]; t3 = fmaxf(t3, 0.f); v.w = t3*t3;
                    *(float4*)(gh + c) = v;
                }
            }
        }
    }
#undef G1_LOAD
}

// -------- GEMM2: out[tok] = gate * (H @ W2 + b2), scatter --------
__global__ __launch_bounds__(256, 2) void kgemm2(
    const float* __restrict__ w2, const float* __restrict__ b2, float* __restrict__ out) {
    const int e  = blockIdx.z;
    const int cnt = g_count[e];
    const int m0 = blockIdx.y * TM;
    if (m0 >= cnt) return;
    const int n0 = blockIdx.x * TN;

    __shared__ float As[2][TK][TM];
    __shared__ float Bs[2][TK][TN];

    const int tid = threadIdx.x;
    const int mA  = tid & 127;
    const int kA  = (tid >> 7) * 4;
    const int nB  = (tid & 31) * 4;
    const int kB  = tid >> 5;
    const int tx4 = (tid & 15) * 4;
    const int ty4 = ((tid >> 4) & 15) * 4;

    const int base = g_base[e];
    const float* arow = g_h + (size_t)(base + m0 + mA) * DFF;   // padded scratch covers overhang
    const float* bcol = w2 + (size_t)e * DFF * C_DIM + n0 + nB;

    float acc[8][8];
#pragma unroll
    for (int ii = 0; ii < 8; ii++)
#pragma unroll
        for (int jj = 0; jj < 8; jj++) acc[ii][jj] = 0.f;

    float4 aR0, aR1, bR0, bR1;

#define G2_LOAD(K0)                                                    \
    aR0 = *(const float4*)(arow + (K0) + kA);                          \
    aR1 = *(const float4*)(arow + (K0) + kA + 8);                      \
    bR0 = *(const float4*)(bcol + (size_t)((K0) + kB) * C_DIM);        \
    bR1 = *(const float4*)(bcol + (size_t)((K0) + kB + 8) * C_DIM);

    G2_LOAD(0); G_STORE(0);
    __syncthreads();
    const int NK = DFF / TK;  // 96
    for (int kc = 0; kc < NK; kc++) {
        const int cur = kc & 1;
        if (kc + 1 < NK) { G2_LOAD((kc + 1) * TK); }
        G_COMPUTE(cur);
        if (kc + 1 < NK) { const int nxt = cur ^ 1; G_STORE(nxt); }
        __syncthreads();
    }

    const float* b2p = b2 + (size_t)e * C_DIM + n0;
#pragma unroll
    for (int ih = 0; ih < 2; ih++) {
#pragma unroll
        for (int i = 0; i < 4; i++) {
            const int r = ih * 64 + ty4 + i;
            const int p = m0 + r;
            if (p < cnt) {
                const int tok  = g_tok[e * CAP + p];
                const float gt = g_gslot[e * CAP + p];
                float* op = out + (size_t)tok * C_DIM + n0;
#pragma unroll
                for (int jh = 0; jh < 2; jh++) {
                    const int c = jh * 64 + tx4;
                    float4 v;
                    v.x = (acc[ih*4+i][jh*4+0] + b2p[c+0]) * gt;
                    v.y = (acc[ih*4+i][jh*4+1] + b2p[c+1]) * gt;
                    v.z = (acc[ih*4+i][jh*4+2] + b2p[c+2]) * gt;
                    v.w = (acc[ih*4+i][jh*4+3] + b2p[c+3]) * gt;
                    *(float4*)(op + c) = v;
                }
            }
        }
    }
#undef G2_LOAD
}

// ---------------------------- launch ----------------------------
extern "C" void kernel_launch(void* const* d_in, const int* in_sizes, int n_in,
                              void* d_out, int out_size) {
    const float* x       = (const float*)d_in[0];
    const float* noise   = (const float*)d_in[1];
    const float* w_route = (const float*)d_in[2];
    const float* b_route = (const float*)d_in[3];
    const float* w_noise = (const float*)d_in[4];
    const float* b_noise = (const float*)d_in[5];
    const float* w1      = (const float*)d_in[6];
    const float* b1      = (const float*)d_in[7];
    const float* w2      = (const float*)d_in[8];
    const float* b2      = (const float*)d_in[9];
    float* out = (float*)d_out;

    const int n4 = NTOK * C_DIM / 4;
    kzero<<<(n4 + 255) / 256, 256>>>((float4*)out, n4);
    kroute<<<NTOK / 8, 256>>>(x, noise, w_route, b_route, w_noise, b_noise);
    kscatter<<<1, 256>>>();
    kgemm1<<<dim3(DFF / TN, CAP / TM, E_NUM), 256>>>(x, w1, b1);
    kgemm2<<<dim3(C_DIM / TN, CAP / TM, E_NUM), 256>>>(w2, b2, out);
}

// round 6
// speedup vs baseline: 1.4048x; 1.4048x over previous
#include <cuda_runtime.h>
#include <cuda_bf16.h>
#include <math.h>
#include <stdint.h>

#define NTOK   32768
#define C_DIM  384
#define E_NUM  8
#define DFF    1536
#define CAP    8192
#define TM     128
#define TN     64
#define KC     32            // bf16 K elems per chunk
#define RS     40            // smem row stride in halfs (80B) -> conflict-free

// ---------------- persistent device scratch ----------------
__device__ int   g_texp[NTOK];
__device__ float g_tgate[NTOK];
__device__ int   g_tok[E_NUM * CAP];
__device__ float g_gslot[E_NUM * CAP];
__device__ int   g_count[E_NUM];
__device__ int   g_base[E_NUM];
__device__ __nv_bfloat16 g_xhi[(size_t)NTOK * C_DIM];
__device__ __nv_bfloat16 g_xlo[(size_t)NTOK * C_DIM];
__device__ __nv_bfloat16 g_w1hi[(size_t)E_NUM * DFF * C_DIM];   // [e][n=dff][k=c]
__device__ __nv_bfloat16 g_w1lo[(size_t)E_NUM * DFF * C_DIM];
__device__ __nv_bfloat16 g_w2hi[(size_t)E_NUM * C_DIM * DFF];   // [e][n=c][k=dff]
__device__ __nv_bfloat16 g_w2lo[(size_t)E_NUM * C_DIM * DFF];
__device__ __nv_bfloat16 g_hhi[(size_t)(NTOK + TM) * DFF];      // H hi plane (padded)
__device__ __nv_bfloat16 g_hlo[(size_t)(NTOK + TM) * DFF];

#define MMA_BF16(D, A0, A1, A2, A3, B0, B1)                                       \
    asm volatile("mma.sync.aligned.m16n8k16.row.col.f32.bf16.bf16.f32 "           \
                 "{%0,%1,%2,%3}, {%4,%5,%6,%7}, {%8,%9}, {%0,%1,%2,%3};"          \
                 : "+f"((D)[0]), "+f"((D)[1]), "+f"((D)[2]), "+f"((D)[3])         \
                 : "r"(A0), "r"(A1), "r"(A2), "r"(A3), "r"(B0), "r"(B1))

// ---------------------------- zero output ----------------------------
__global__ __launch_bounds__(256) void kzero(float4* __restrict__ out, int n4) {
    int i = blockIdx.x * blockDim.x + threadIdx.x;
    if (i < n4) out[i] = make_float4(0.f, 0.f, 0.f, 0.f);
}

// ------------------- x -> bf16 hi/lo planes -------------------
__global__ __launch_bounds__(256) void kconv_x(const float2* __restrict__ x2) {
    int i = blockIdx.x * blockDim.x + threadIdx.x;
    float2 v = x2[i];
    __nv_bfloat16 h0 = __float2bfloat16(v.x);
    __nv_bfloat16 h1 = __float2bfloat16(v.y);
    __nv_bfloat16 l0 = __float2bfloat16(v.x - __bfloat162float(h0));
    __nv_bfloat16 l1 = __float2bfloat16(v.y - __bfloat162float(h1));
    ((__nv_bfloat162*)g_xhi)[i] = __nv_bfloat162(h0, h1);
    ((__nv_bfloat162*)g_xlo)[i] = __nv_bfloat162(l0, l1);
}

// ---- transpose + split: in [e][R][C] fp32 -> symbol planes [e][C][R] bf16 ----
// which=0 -> g_w1hi/g_w1lo, which=1 -> g_w2hi/g_w2lo.
// NOTE: output symbols are bound in DEVICE code (host-passed __device__ symbol
// addresses are invalid; on GB300/ATS they silently alias host memory).
__global__ __launch_bounds__(256) void ktrans(const float* __restrict__ in,
                                              int which, int R, int C) {
    __nv_bfloat16* __restrict__ ohi = which ? g_w2hi : g_w1hi;
    __nv_bfloat16* __restrict__ olo = which ? g_w2lo : g_w1lo;
    __shared__ float tile[32][33];
    const int bx = blockIdx.x, by = blockIdx.y, e = blockIdx.z;
    const int tx = threadIdx.x, ty = threadIdx.y;   // 32 x 8
    const float* ip = in + (size_t)e * R * C;
#pragma unroll
    for (int i = 0; i < 4; i++)
        tile[ty + 8 * i][tx] = ip[(size_t)(by * 32 + ty + 8 * i) * C + bx * 32 + tx];
    __syncthreads();
    const size_t op = (size_t)e * R * C;
#pragma unroll
    for (int i = 0; i < 4; i++) {
        float v = tile[tx][ty + 8 * i];
        __nv_bfloat16 h = __float2bfloat16(v);
        __nv_bfloat16 l = __float2bfloat16(v - __bfloat162float(h));
        size_t idx = op + (size_t)(bx * 32 + ty + 8 * i) * R + by * 32 + tx;
        ohi[idx] = h;
        olo[idx] = l;
    }
}

// ---------------------------- routing ----------------------------
__global__ __launch_bounds__(256) void kroute(
        const float* __restrict__ x, const float* __restrict__ noise,
        const float* __restrict__ w_route, const float* __restrict__ b_route,
        const float* __restrict__ w_noise, const float* __restrict__ b_noise) {
    __shared__ float swr[E_NUM * C_DIM];
    __shared__ float swn[E_NUM * C_DIM];
    for (int i = threadIdx.x; i < E_NUM * C_DIM; i += blockDim.x) {
        int c = i >> 3, e = i & 7;
        swr[e * C_DIM + c] = w_route[i];
        swn[e * C_DIM + c] = w_noise[i];
    }
    __syncthreads();
    const int lane = threadIdx.x & 31;
    const int warp = threadIdx.x >> 5;
    const int t = blockIdx.x * 8 + warp;

    float ar[E_NUM], an[E_NUM];
#pragma unroll
    for (int e = 0; e < E_NUM; e++) { ar[e] = 0.f; an[e] = 0.f; }
    const float* xr = x + (size_t)t * C_DIM;
#pragma unroll
    for (int j = 0; j < C_DIM / 32; j++) {
        const int c = j * 32 + lane;
        const float xv = xr[c];
#pragma unroll
        for (int e = 0; e < E_NUM; e++) {
            ar[e] = fmaf(xv, swr[e * C_DIM + c], ar[e]);
            an[e] = fmaf(xv, swn[e * C_DIM + c], an[e]);
        }
    }
#pragma unroll
    for (int e = 0; e < E_NUM; e++) {
#pragma unroll
        for (int off = 16; off > 0; off >>= 1) {
            ar[e] += __shfl_xor_sync(0xffffffffu, ar[e], off);
            an[e] += __shfl_xor_sync(0xffffffffu, an[e], off);
        }
    }
    if (lane == 0) {
        float ns[E_NUM];
        float best = -INFINITY; int bi = 0;
#pragma unroll
        for (int e = 0; e < E_NUM; e++) {
            float lg = ar[e] + b_route[e];
            float z  = an[e] + b_noise[e];
            float sp = fmaxf(z, 0.f) + log1pf(expf(-fabsf(z)));
            ns[e] = lg + noise[(size_t)t * E_NUM + e] * sp;
            if (ns[e] > best) { best = ns[e]; bi = e; }
        }
        float second = -INFINITY;
#pragma unroll
        for (int e = 0; e < E_NUM; e++)
            if (e != bi && ns[e] > second) second = ns[e];
        g_texp[t]  = bi;
        g_tgate[t] = 1.f / (1.f + expf(second - best));
    }
}

// ------------------ ordered compaction (single block, 256 thr) ------------------
__global__ __launch_bounds__(256) void kscatter() {
    __shared__ int s[E_NUM][256];
    __shared__ int stot[E_NUM];
    const int tid = threadIdx.x;
    const int CH  = NTOK / 256;
    const int t0  = tid * CH;

    int cnt[E_NUM];
#pragma unroll
    for (int e = 0; e < E_NUM; e++) cnt[e] = 0;
    for (int i = 0; i < CH; i++) cnt[g_texp[t0 + i]]++;
#pragma unroll
    for (int e = 0; e < E_NUM; e++) s[e][tid] = cnt[e];
    __syncthreads();
    for (int off = 1; off < 256; off <<= 1) {
        int v[E_NUM];
#pragma unroll
        for (int e = 0; e < E_NUM; e++) v[e] = (tid >= off) ? s[e][tid - off] : 0;
        __syncthreads();
#pragma unroll
        for (int e = 0; e < E_NUM; e++) s[e][tid] += v[e];
        __syncthreads();
    }
    int run[E_NUM];
#pragma unroll
    for (int e = 0; e < E_NUM; e++) run[e] = s[e][tid] - cnt[e];
    if (tid < E_NUM) stot[tid] = s[tid][255];
    __syncthreads();
    if (tid == 0) {
        int b = 0;
        for (int e = 0; e < E_NUM; e++) {
            int c = stot[e] < CAP ? stot[e] : CAP;
            g_count[e] = c;
            g_base[e]  = b;
            b += c;
        }
    }
    for (int i = 0; i < CH; i++) {
        int t = t0 + i;
        int e = g_texp[t];
        int p = run[e]++;
        if (p < CAP) {
            g_tok[e * CAP + p]   = t;
            g_gslot[e * CAP + p] = g_tgate[t];
        }
    }
}

// ========== explicit-LDS fragment + mma block (one K-chunk of 32) ==========
// Fragment formulas (PTX m16n8k16):
//   a0: (m=fr, k=fc)  a1: (m=fr+8, k=fc)  a2: (m=fr, k=fc+8)  a3: (m=fr+8, k=fc+8)
//   b0: (n=fr, k=fc)  b1: (n=fr, k=fc+8)
#define FRAG_MMA_BLOCK()                                                          \
    _Pragma("unroll")                                                             \
    for (int ks = 0; ks < 2; ks++) {                                              \
        uint32_t b0h[2], b1h[2], b0l[2], b1l[2];                                  \
        _Pragma("unroll")                                                         \
        for (int j = 0; j < 2; j++) {                                             \
            const int bn = (wn * 16 + j * 8 + fr) * RS + ks * 16 + fc;            \
            b0h[j] = *(const uint32_t*)&sBh[bn];                                  \
            b1h[j] = *(const uint32_t*)&sBh[bn + 8];                              \
            b0l[j] = *(const uint32_t*)&sBl[bn];                                  \
            b1l[j] = *(const uint32_t*)&sBl[bn + 8];                              \
        }                                                                         \
        _Pragma("unroll")                                                         \
        for (int mt = 0; mt < 4; mt++) {                                          \
            const int ar = (wm * 64 + mt * 16 + fr) * RS + ks * 16 + fc;          \
            uint32_t a0 = *(const uint32_t*)&sAh[ar];                             \
            uint32_t a1 = *(const uint32_t*)&sAh[ar + 8 * RS];                    \
            uint32_t a2 = *(const uint32_t*)&sAh[ar + 8];                         \
            uint32_t a3 = *(const uint32_t*)&sAh[ar + 8 * RS + 8];                \
            uint32_t l0 = *(const uint32_t*)&sAl[ar];                             \
            uint32_t l1 = *(const uint32_t*)&sAl[ar + 8 * RS];                    \
            uint32_t l2 = *(const uint32_t*)&sAl[ar + 8];                         \
            uint32_t l3 = *(const uint32_t*)&sAl[ar + 8 * RS + 8];                \
            _Pragma("unroll")                                                     \
            for (int j = 0; j < 2; j++) {                                         \
                MMA_BF16(acc[mt][j], a0, a1, a2, a3, b0h[j], b1h[j]);             \
                MMA_BF16(acc[mt][j], l0, l1, l2, l3, b0h[j], b1h[j]);             \
                MMA_BF16(acc[mt][j], a0, a1, a2, a3, b0l[j], b1l[j]);             \
            }                                                                     \
        }                                                                         \
    }

#define SMEM_DECL                                                                 \
    __shared__ __align__(16) __nv_bfloat16 sAh[TM * RS];                          \
    __shared__ __align__(16) __nv_bfloat16 sAl[TM * RS];                          \
    __shared__ __align__(16) __nv_bfloat16 sBh[TN * RS];                          \
    __shared__ __align__(16) __nv_bfloat16 sBl[TN * RS];

#define STORE_CHUNK()                                                             \
    *(uint4*)&sAh[sOffA0] = pah0;                                                 \
    *(uint4*)&sAh[sOffA1] = pah1;                                                 \
    *(uint4*)&sAl[sOffA0] = pal0;                                                 \
    *(uint4*)&sAl[sOffA1] = pal1;                                                 \
    *(uint4*)&sBh[sOffB]  = pbh;                                                  \
    *(uint4*)&sBl[sOffB]  = pbl;

// ----------------- GEMM1: H = relu(Xg @ W1 + b1)^2 (bf16 split out) -----------------
__global__ __launch_bounds__(256, 2) void kgemm1_mma(const float* __restrict__ b1) {
    const int e   = blockIdx.z;
    const int cnt = g_count[e];
    const int m0  = blockIdx.y * TM;
    if (m0 >= cnt) return;
    const int n0  = blockIdx.x * TN;

    SMEM_DECL
    const int tid  = threadIdx.x;
    const int lane = tid & 31;
    const int wid  = tid >> 5;
    const int wm   = wid >> 2;          // 0..1
    const int wn   = wid & 3;           // 0..3
    const int fr   = lane >> 2;         // 0..7
    const int fc   = (lane & 3) * 2;    // 0,2,4,6

    const int rA0 = tid >> 2;           // 0..63
    const int cA0 = tid & 3;            // chunk of 8 halfs
    const int rA1 = rA0 + 64;
    const int sOffA0 = rA0 * RS + cA0 * 8;
    const int sOffA1 = rA1 * RS + cA0 * 8;
    const int sOffB  = sOffA0;

    const int tk0 = g_tok[e * CAP + m0 + rA0];
    const int tk1 = g_tok[e * CAP + m0 + rA1];
    const size_t aOff0 = (size_t)tk0 * C_DIM + cA0 * 8;
    const size_t aOff1 = (size_t)tk1 * C_DIM + cA0 * 8;
    const size_t bOff  = (size_t)(e * DFF + n0 + rA0) * C_DIM + cA0 * 8;

    float acc[4][2][4];
#pragma unroll
    for (int a = 0; a < 4; a++)
#pragma unroll
        for (int b = 0; b < 2; b++)
#pragma unroll
            for (int c = 0; c < 4; c++) acc[a][b][c] = 0.f;

    uint4 pah0, pah1, pal0, pal1, pbh, pbl;
#define G1_LOAD(K0)                                                   \
    pah0 = *(const uint4*)(g_xhi + aOff0 + (K0));                     \
    pah1 = *(const uint4*)(g_xhi + aOff1 + (K0));                     \
    pal0 = *(const uint4*)(g_xlo + aOff0 + (K0));                     \
    pal1 = *(const uint4*)(g_xlo + aOff1 + (K0));                     \
    pbh  = *(const uint4*)(g_w1hi + bOff + (K0));                     \
    pbl  = *(const uint4*)(g_w1lo + bOff + (K0));

    G1_LOAD(0);
    const int NK = C_DIM / KC;   // 12
    for (int kci = 0; kci < NK; kci++) {
        STORE_CHUNK();
        __syncthreads();
        if (kci + 1 < NK) { G1_LOAD((kci + 1) * KC); }
        FRAG_MMA_BLOCK();
        __syncthreads();
    }
#undef G1_LOAD

    // epilogue: bias + relu^2 + hi/lo split -> g_hhi/g_hlo
    const int gb = g_base[e];
    const int c0 = wn * 16 + fc;
    const float* b1p = b1 + (size_t)e * DFF + n0;
    float2 bj0 = *(const float2*)(b1p + c0);
    float2 bj1 = *(const float2*)(b1p + c0 + 8);
#pragma unroll
    for (int mt = 0; mt < 4; mt++) {
#pragma unroll
        for (int hf = 0; hf < 2; hf++) {
            const int r = wm * 64 + mt * 16 + fr + hf * 8;
            const int p = m0 + r;
            if (p < cnt) {
                __nv_bfloat16* hh = g_hhi + (size_t)(gb + p) * DFF + n0;
                __nv_bfloat16* hl = g_hlo + (size_t)(gb + p) * DFF + n0;
#pragma unroll
                for (int j = 0; j < 2; j++) {
                    float v0 = acc[mt][j][hf * 2]     + (j ? bj1.x : bj0.x);
                    float v1 = acc[mt][j][hf * 2 + 1] + (j ? bj1.y : bj0.y);
                    v0 = fmaxf(v0, 0.f); v0 *= v0;
                    v1 = fmaxf(v1, 0.f); v1 *= v1;
                    __nv_bfloat16 h0 = __float2bfloat16(v0);
                    __nv_bfloat16 h1 = __float2bfloat16(v1);
                    __nv_bfloat16 l0 = __float2bfloat16(v0 - __bfloat162float(h0));
                    __nv_bfloat16 l1 = __float2bfloat16(v1 - __bfloat162float(h1));
                    *(__nv_bfloat162*)(hh + c0 + j * 8) = __nv_bfloat162(h0, h1);
                    *(__nv_bfloat162*)(hl + c0 + j * 8) = __nv_bfloat162(l0, l1);
                }
            }
        }
    }
}

// -------- GEMM2: out[tok] = gate * (H @ W2 + b2), scatter --------
__global__ __launch_bounds__(256, 2) void kgemm2_mma(const float* __restrict__ b2,
                                                     float* __restrict__ out) {
    const int e   = blockIdx.z;
    const int cnt = g_count[e];
    const int m0  = blockIdx.y * TM;
    if (m0 >= cnt) return;
    const int n0  = blockIdx.x * TN;

    SMEM_DECL
    const int tid  = threadIdx.x;
    const int lane = tid & 31;
    const int wid  = tid >> 5;
    const int wm   = wid >> 2;
    const int wn   = wid & 3;
    const int fr   = lane >> 2;
    const int fc   = (lane & 3) * 2;

    const int rA0 = tid >> 2;
    const int cA0 = tid & 3;
    const int rA1 = rA0 + 64;
    const int sOffA0 = rA0 * RS + cA0 * 8;
    const int sOffA1 = rA1 * RS + cA0 * 8;
    const int sOffB  = sOffA0;

    const int gb = g_base[e];
    const size_t aOff0 = (size_t)(gb + m0 + rA0) * DFF + cA0 * 8;
    const size_t aOff1 = (size_t)(gb + m0 + rA1) * DFF + cA0 * 8;
    const size_t bOff  = (size_t)(e * C_DIM + n0 + rA0) * DFF + cA0 * 8;

    float acc[4][2][4];
#pragma unroll
    for (int a = 0; a < 4; a++)
#pragma unroll
        for (int b = 0; b < 2; b++)
#pragma unroll
            for (int c = 0; c < 4; c++) acc[a][b][c] = 0.f;

    uint4 pah0, pah1, pal0, pal1, pbh, pbl;
#define G2_LOAD(K0)                                                   \
    pah0 = *(const uint4*)(g_hhi + aOff0 + (K0));                     \
    pah1 = *(const uint4*)(g_hhi + aOff1 + (K0));                     \
    pal0 = *(const uint4*)(g_hlo + aOff0 + (K0));                     \
    pal1 = *(const uint4*)(g_hlo + aOff1 + (K0));                     \
    pbh  = *(const uint4*)(g_w2hi + bOff + (K0));                     \
    pbl  = *(const uint4*)(g_w2lo + bOff + (K0));

    G2_LOAD(0);
    const int NK = DFF / KC;   // 48
    for (int kci = 0; kci < NK; kci++) {
        STORE_CHUNK();
        __syncthreads();
        if (kci + 1 < NK) { G2_LOAD((kci + 1) * KC); }
        FRAG_MMA_BLOCK();
        __syncthreads();
    }
#undef G2_LOAD

    const int c0 = wn * 16 + fc;
    const float* b2p = b2 + (size_t)e * C_DIM + n0;
    float2 bj0 = *(const float2*)(b2p + c0);
    float2 bj1 = *(const float2*)(b2p + c0 + 8);
#pragma unroll
    for (int mt = 0; mt < 4; mt++) {
#pragma unroll
        for (int hf = 0; hf < 2; hf++) {
            const int r = wm * 64 + mt * 16 + fr + hf * 8;
            const int p = m0 + r;
            if (p < cnt) {
                const int tok  = g_tok[e * CAP + p];
                const float gt = g_gslot[e * CAP + p];
                float* op = out + (size_t)tok * C_DIM + n0 + c0;
                float2 v0, v1;
                v0.x = (acc[mt][0][hf * 2]     + bj0.x) * gt;
                v0.y = (acc[mt][0][hf * 2 + 1] + bj0.y) * gt;
                v1.x = (acc[mt][1][hf * 2]     + bj1.x) * gt;
                v1.y = (acc[mt][1][hf * 2 + 1] + bj1.y) * gt;
                *(float2*)op       = v0;
                *(float2*)(op + 8) = v1;
            }
        }
    }
}

// ---------------------------- launch ----------------------------
extern "C" void kernel_launch(void* const* d_in, const int* in_sizes, int n_in,
                              void* d_out, int out_size) {
    const float* x       = (const float*)d_in[0];
    const float* noise   = (const float*)d_in[1];
    const float* w_route = (const float*)d_in[2];
    const float* b_route = (const float*)d_in[3];
    const float* w_noise = (const float*)d_in[4];
    const float* b_noise = (const float*)d_in[5];
    const float* w1      = (const float*)d_in[6];
    const float* b1      = (const float*)d_in[7];
    const float* w2      = (const float*)d_in[8];
    const float* b2      = (const float*)d_in[9];
    float* out = (float*)d_out;

    const int n4 = NTOK * C_DIM / 4;
    kzero<<<(n4 + 255) / 256, 256>>>((float4*)out, n4);
    kconv_x<<<(NTOK * C_DIM / 2 + 255) / 256, 256>>>((const float2*)x);
    ktrans<<<dim3(DFF / 32, C_DIM / 32, E_NUM), dim3(32, 8)>>>(w1, 0, C_DIM, DFF);
    ktrans<<<dim3(C_DIM / 32, DFF / 32, E_NUM), dim3(32, 8)>>>(w2, 1, DFF, C_DIM);
    kroute<<<NTOK / 8, 256>>>(x, noise, w_route, b_route, w_noise, b_noise);
    kscatter<<<1, 256>>>();
    kgemm1_mma<<<dim3(DFF / TN, CAP / TM, E_NUM), 256>>>(b1);
    kgemm2_mma<<<dim3(C_DIM / TN, CAP / TM, E_NUM), 256>>>(b2, out);
}

// round 7
// speedup vs baseline: 1.5896x; 1.1315x over previous
#include <cuda_runtime.h>
#include <cuda_bf16.h>
#include <math.h>
#include <stdint.h>

#define NTOK   32768
#define C_DIM  384
#define E_NUM  8
#define DFF    1536
#define CAP    8192
#define TM     128
#define TN     64
#define KC     32            // bf16 K elems per chunk
#define RS     40            // smem row stride in halfs (80B) -> conflict-free

// ---------------- persistent device scratch ----------------
__device__ int   g_texp[NTOK];
__device__ float g_tgate[NTOK];
__device__ int   g_tok[E_NUM * CAP];
__device__ float g_gslot[E_NUM * CAP];
__device__ int   g_count[E_NUM];
__device__ int   g_base[E_NUM];
__device__ __nv_bfloat16 g_xhi[(size_t)NTOK * C_DIM];
__device__ __nv_bfloat16 g_xlo[(size_t)NTOK * C_DIM];
__device__ __nv_bfloat16 g_w1hi[(size_t)E_NUM * DFF * C_DIM];   // [e][n=dff][k=c]
__device__ __nv_bfloat16 g_w1lo[(size_t)E_NUM * DFF * C_DIM];
__device__ __nv_bfloat16 g_w2hi[(size_t)E_NUM * C_DIM * DFF];   // [e][n=c][k=dff]
__device__ __nv_bfloat16 g_w2lo[(size_t)E_NUM * C_DIM * DFF];
__device__ __nv_bfloat16 g_hhi[(size_t)(NTOK + TM) * DFF];      // H hi plane (padded)
__device__ __nv_bfloat16 g_hlo[(size_t)(NTOK + TM) * DFF];

__device__ __forceinline__ uint32_t smem_to_u32(const void* p) {
    uint32_t a;
    asm("{ .reg .u64 t; cvta.to.shared.u64 t, %1; cvt.u32.u64 %0, t; }" : "=r"(a) : "l"(p));
    return a;
}

#define LDSM_X4(R0, R1, R2, R3, ADDR)                                             \
    asm volatile("ldmatrix.sync.aligned.m8n8.x4.shared.b16 {%0,%1,%2,%3}, [%4];"  \
                 : "=r"(R0), "=r"(R1), "=r"(R2), "=r"(R3) : "r"(ADDR))

#define MMA_BF16(D, A0, A1, A2, A3, B0, B1)                                       \
    asm volatile("mma.sync.aligned.m16n8k16.row.col.f32.bf16.bf16.f32 "           \
                 "{%0,%1,%2,%3}, {%4,%5,%6,%7}, {%8,%9}, {%0,%1,%2,%3};"          \
                 : "+f"((D)[0]), "+f"((D)[1]), "+f"((D)[2]), "+f"((D)[3])         \
                 : "r"(A0), "r"(A1), "r"(A2), "r"(A3), "r"(B0), "r"(B1))

// ---------------------------- zero output ----------------------------
__global__ __launch_bounds__(256) void kzero(float4* __restrict__ out, int n4) {
    int i = blockIdx.x * blockDim.x + threadIdx.x;
    if (i < n4) out[i] = make_float4(0.f, 0.f, 0.f, 0.f);
}

// ------------------- x -> bf16 hi/lo planes -------------------
__global__ __launch_bounds__(256) void kconv_x(const float2* __restrict__ x2) {
    int i = blockIdx.x * blockDim.x + threadIdx.x;
    float2 v = x2[i];
    __nv_bfloat16 h0 = __float2bfloat16(v.x);
    __nv_bfloat16 h1 = __float2bfloat16(v.y);
    __nv_bfloat16 l0 = __float2bfloat16(v.x - __bfloat162float(h0));
    __nv_bfloat16 l1 = __float2bfloat16(v.y - __bfloat162float(h1));
    ((__nv_bfloat162*)g_xhi)[i] = __nv_bfloat162(h0, h1);
    ((__nv_bfloat162*)g_xlo)[i] = __nv_bfloat162(l0, l1);
}

// ---- transpose + split: in [e][R][C] fp32 -> symbol planes [e][C][R] bf16 ----
// which=0 -> g_w1hi/g_w1lo, which=1 -> g_w2hi/g_w2lo (bound in DEVICE code).
__global__ __launch_bounds__(256) void ktrans(const float* __restrict__ in,
                                              int which, int R, int C) {
    __nv_bfloat16* __restrict__ ohi = which ? g_w2hi : g_w1hi;
    __nv_bfloat16* __restrict__ olo = which ? g_w2lo : g_w1lo;
    __shared__ float tile[32][33];
    const int bx = blockIdx.x, by = blockIdx.y, e = blockIdx.z;
    const int tx = threadIdx.x, ty = threadIdx.y;   // 32 x 8
    const float* ip = in + (size_t)e * R * C;
#pragma unroll
    for (int i = 0; i < 4; i++)
        tile[ty + 8 * i][tx] = ip[(size_t)(by * 32 + ty + 8 * i) * C + bx * 32 + tx];
    __syncthreads();
    const size_t op = (size_t)e * R * C;
#pragma unroll
    for (int i = 0; i < 4; i++) {
        float v = tile[tx][ty + 8 * i];
        __nv_bfloat16 h = __float2bfloat16(v);
        __nv_bfloat16 l = __float2bfloat16(v - __bfloat162float(h));
        size_t idx = op + (size_t)(bx * 32 + ty + 8 * i) * R + by * 32 + tx;
        ohi[idx] = h;
        olo[idx] = l;
    }
}

// ---------------------------- routing ----------------------------
__global__ __launch_bounds__(256) void kroute(
        const float* __restrict__ x, const float* __restrict__ noise,
        const float* __restrict__ w_route, const float* __restrict__ b_route,
        const float* __restrict__ w_noise, const float* __restrict__ b_noise) {
    __shared__ float swr[E_NUM * C_DIM];
    __shared__ float swn[E_NUM * C_DIM];
    for (int i = threadIdx.x; i < E_NUM * C_DIM; i += blockDim.x) {
        int c = i >> 3, e = i & 7;
        swr[e * C_DIM + c] = w_route[i];
        swn[e * C_DIM + c] = w_noise[i];
    }
    __syncthreads();
    const int lane = threadIdx.x & 31;
    const int warp = threadIdx.x >> 5;
    const int t = blockIdx.x * 8 + warp;

    float ar[E_NUM], an[E_NUM];
#pragma unroll
    for (int e = 0; e < E_NUM; e++) { ar[e] = 0.f; an[e] = 0.f; }
    const float* xr = x + (size_t)t * C_DIM;
#pragma unroll
    for (int j = 0; j < C_DIM / 32; j++) {
        const int c = j * 32 + lane;
        const float xv = xr[c];
#pragma unroll
        for (int e = 0; e < E_NUM; e++) {
            ar[e] = fmaf(xv, swr[e * C_DIM + c], ar[e]);
            an[e] = fmaf(xv, swn[e * C_DIM + c], an[e]);
        }
    }
#pragma unroll
    for (int e = 0; e < E_NUM; e++) {
#pragma unroll
        for (int off = 16; off > 0; off >>= 1) {
            ar[e] += __shfl_xor_sync(0xffffffffu, ar[e], off);
            an[e] += __shfl_xor_sync(0xffffffffu, an[e], off);
        }
    }
    if (lane == 0) {
        float ns[E_NUM];
        float best = -INFINITY; int bi = 0;
#pragma unroll
        for (int e = 0; e < E_NUM; e++) {
            float lg = ar[e] + b_route[e];
            float z  = an[e] + b_noise[e];
            float sp = fmaxf(z, 0.f) + log1pf(expf(-fabsf(z)));
            ns[e] = lg + noise[(size_t)t * E_NUM + e] * sp;
            if (ns[e] > best) { best = ns[e]; bi = e; }
        }
        float second = -INFINITY;
#pragma unroll
        for (int e = 0; e < E_NUM; e++)
            if (e != bi && ns[e] > second) second = ns[e];
        g_texp[t]  = bi;
        g_tgate[t] = 1.f / (1.f + expf(second - best));
    }
}

// ------------------ ordered compaction (single block, 256 thr) ------------------
__global__ __launch_bounds__(256) void kscatter() {
    __shared__ int s[E_NUM][256];
    __shared__ int stot[E_NUM];
    const int tid = threadIdx.x;
    const int CH  = NTOK / 256;
    const int t0  = tid * CH;

    int cnt[E_NUM];
#pragma unroll
    for (int e = 0; e < E_NUM; e++) cnt[e] = 0;
    for (int i = 0; i < CH; i++) cnt[g_texp[t0 + i]]++;
#pragma unroll
    for (int e = 0; e < E_NUM; e++) s[e][tid] = cnt[e];
    __syncthreads();
    for (int off = 1; off < 256; off <<= 1) {
        int v[E_NUM];
#pragma unroll
        for (int e = 0; e < E_NUM; e++) v[e] = (tid >= off) ? s[e][tid - off] : 0;
        __syncthreads();
#pragma unroll
        for (int e = 0; e < E_NUM; e++) s[e][tid] += v[e];
        __syncthreads();
    }
    int run[E_NUM];
#pragma unroll
    for (int e = 0; e < E_NUM; e++) run[e] = s[e][tid] - cnt[e];
    if (tid < E_NUM) stot[tid] = s[tid][255];
    __syncthreads();
    if (tid == 0) {
        int b = 0;
        for (int e = 0; e < E_NUM; e++) {
            int c = stot[e] < CAP ? stot[e] : CAP;
            g_count[e] = c;
            g_base[e]  = b;
            b += c;
        }
    }
    for (int i = 0; i < CH; i++) {
        int t = t0 + i;
        int e = g_texp[t];
        int p = run[e]++;
        if (p < CAP) {
            g_tok[e * CAP + p]   = t;
            g_gslot[e * CAP + p] = g_tgate[t];
        }
    }
}

// ========== ldmatrix fragment + mma block (one K-chunk of 32) ==========
// A ldmatrix.x4 lane map: rows (lane&15), col half-block (lane>>4) -> {a0,a1,a2,a3}
// B ldmatrix.x4 lane map: lanes 0-7: n0-7/k0-7, 8-15: n0-7/k8-15,
//                         16-23: n8-15/k0-7, 24-31: n8-15/k8-15 -> {j0b0,j0b1,j1b0,j1b1}
#define FRAG_MMA_BLOCK()                                                          \
    _Pragma("unroll")                                                             \
    for (int ks = 0; ks < 2; ks++) {                                              \
        uint32_t bh[4], bl[4];                                                    \
        LDSM_X4(bh[0], bh[1], bh[2], bh[3], bBaseH + ks * 32);                    \
        LDSM_X4(bl[0], bl[1], bl[2], bl[3], bBaseL + ks * 32);                    \
        _Pragma("unroll")                                                         \
        for (int mt = 0; mt < 4; mt++) {                                          \
            uint32_t ah[4], al[4];                                                \
            LDSM_X4(ah[0], ah[1], ah[2], ah[3],                                   \
                    aBaseH + mt * (16 * RS * 2) + ks * 32);                       \
            LDSM_X4(al[0], al[1], al[2], al[3],                                   \
                    aBaseL + mt * (16 * RS * 2) + ks * 32);                       \
            _Pragma("unroll")                                                     \
            for (int j = 0; j < 2; j++) {                                         \
                MMA_BF16(acc[mt][j], ah[0], ah[1], ah[2], ah[3],                  \
                         bh[2 * j], bh[2 * j + 1]);                               \
                MMA_BF16(acc[mt][j], al[0], al[1], al[2], al[3],                  \
                         bh[2 * j], bh[2 * j + 1]);                               \
                MMA_BF16(acc[mt][j], ah[0], ah[1], ah[2], ah[3],                  \
                         bl[2 * j], bl[2 * j + 1]);                               \
            }                                                                     \
        }                                                                         \
    }

#define SMEM_DECL                                                                 \
    __shared__ __align__(16) __nv_bfloat16 sAh[TM * RS];                          \
    __shared__ __align__(16) __nv_bfloat16 sAl[TM * RS];                          \
    __shared__ __align__(16) __nv_bfloat16 sBh[TN * RS];                          \
    __shared__ __align__(16) __nv_bfloat16 sBl[TN * RS];

#define FRAG_ADDR_DECL                                                            \
    const uint32_t aBaseH = smem_to_u32(sAh) +                                    \
        (uint32_t)(((wm * 64 + (lane & 15)) * RS + (lane >> 4) * 8) * 2);         \
    const uint32_t aBaseL = smem_to_u32(sAl) +                                    \
        (uint32_t)(((wm * 64 + (lane & 15)) * RS + (lane >> 4) * 8) * 2);         \
    const uint32_t bBaseH = smem_to_u32(sBh) +                                    \
        (uint32_t)(((wn * 16 + (lane & 7) + ((lane >> 4) & 1) * 8) * RS +         \
                    ((lane >> 3) & 1) * 8) * 2);                                  \
    const uint32_t bBaseL = smem_to_u32(sBl) +                                    \
        (uint32_t)(((wn * 16 + (lane & 7) + ((lane >> 4) & 1) * 8) * RS +         \
                    ((lane >> 3) & 1) * 8) * 2);

#define STORE_CHUNK()                                                             \
    *(uint4*)&sAh[sOffA0] = pah0;                                                 \
    *(uint4*)&sAh[sOffA1] = pah1;                                                 \
    *(uint4*)&sAl[sOffA0] = pal0;                                                 \
    *(uint4*)&sAl[sOffA1] = pal1;                                                 \
    *(uint4*)&sBh[sOffB]  = pbh;                                                  \
    *(uint4*)&sBl[sOffB]  = pbl;

// ----------------- GEMM1: H = relu(Xg @ W1 + b1)^2 (bf16 split out) -----------------
__global__ __launch_bounds__(256, 2) void kgemm1_mma(const float* __restrict__ b1) {
    const int e   = blockIdx.z;
    const int cnt = g_count[e];
    const int m0  = blockIdx.y * TM;
    if (m0 >= cnt) return;
    const int n0  = blockIdx.x * TN;

    SMEM_DECL
    const int tid  = threadIdx.x;
    const int lane = tid & 31;
    const int wid  = tid >> 5;
    const int wm   = wid >> 2;          // 0..1
    const int wn   = wid & 3;           // 0..3
    const int fr   = lane >> 2;         // 0..7
    const int fc   = (lane & 3) * 2;    // 0,2,4,6
    FRAG_ADDR_DECL

    const int rA0 = tid >> 2;           // 0..63
    const int cA0 = tid & 3;            // chunk of 8 halfs
    const int rA1 = rA0 + 64;
    const int sOffA0 = rA0 * RS + cA0 * 8;
    const int sOffA1 = rA1 * RS + cA0 * 8;
    const int sOffB  = sOffA0;

    const int tk0 = g_tok[e * CAP + m0 + rA0];
    const int tk1 = g_tok[e * CAP + m0 + rA1];
    const size_t aOff0 = (size_t)tk0 * C_DIM + cA0 * 8;
    const size_t aOff1 = (size_t)tk1 * C_DIM + cA0 * 8;
    const size_t bOff  = (size_t)(e * DFF + n0 + rA0) * C_DIM + cA0 * 8;

    float acc[4][2][4];
#pragma unroll
    for (int a = 0; a < 4; a++)
#pragma unroll
        for (int b = 0; b < 2; b++)
#pragma unroll
            for (int c = 0; c < 4; c++) acc[a][b][c] = 0.f;

    uint4 pah0, pah1, pal0, pal1, pbh, pbl;
#define G1_LOAD(K0)                                                   \
    pah0 = *(const uint4*)(g_xhi + aOff0 + (K0));                     \
    pah1 = *(const uint4*)(g_xhi + aOff1 + (K0));                     \
    pal0 = *(const uint4*)(g_xlo + aOff0 + (K0));                     \
    pal1 = *(const uint4*)(g_xlo + aOff1 + (K0));                     \
    pbh  = *(const uint4*)(g_w1hi + bOff + (K0));                     \
    pbl  = *(const uint4*)(g_w1lo + bOff + (K0));

    G1_LOAD(0);
    const int NK = C_DIM / KC;   // 12
    for (int kci = 0; kci < NK; kci++) {
        STORE_CHUNK();
        __syncthreads();
        if (kci + 1 < NK) { G1_LOAD((kci + 1) * KC); }
        FRAG_MMA_BLOCK();
        __syncthreads();
    }
#undef G1_LOAD

    // epilogue: bias + relu^2 + hi/lo split -> g_hhi/g_hlo
    const int gb = g_base[e];
    const int c0 = wn * 16 + fc;
    const float* b1p = b1 + (size_t)e * DFF + n0;
    float2 bj0 = *(const float2*)(b1p + c0);
    float2 bj1 = *(const float2*)(b1p + c0 + 8);
#pragma unroll
    for (int mt = 0; mt < 4; mt++) {
#pragma unroll
        for (int hf = 0; hf < 2; hf++) {
            const int r = wm * 64 + mt * 16 + fr + hf * 8;
            const int p = m0 + r;
            if (p < cnt) {
                __nv_bfloat16* hh = g_hhi + (size_t)(gb + p) * DFF + n0;
                __nv_bfloat16* hl = g_hlo + (size_t)(gb + p) * DFF + n0;
#pragma unroll
                for (int j = 0; j < 2; j++) {
                    float v0 = acc[mt][j][hf * 2]     + (j ? bj1.x : bj0.x);
                    float v1 = acc[mt][j][hf * 2 + 1] + (j ? bj1.y : bj0.y);
                    v0 = fmaxf(v0, 0.f); v0 *= v0;
                    v1 = fmaxf(v1, 0.f); v1 *= v1;
                    __nv_bfloat16 h0 = __float2bfloat16(v0);
                    __nv_bfloat16 h1 = __float2bfloat16(v1);
                    __nv_bfloat16 l0 = __float2bfloat16(v0 - __bfloat162float(h0));
                    __nv_bfloat16 l1 = __float2bfloat16(v1 - __bfloat162float(h1));
                    *(__nv_bfloat162*)(hh + c0 + j * 8) = __nv_bfloat162(h0, h1);
                    *(__nv_bfloat162*)(hl + c0 + j * 8) = __nv_bfloat162(l0, l1);
                }
            }
        }
    }
}

// -------- GEMM2: out[tok] = gate * (H @ W2 + b2), scatter --------
__global__ __launch_bounds__(256, 2) void kgemm2_mma(const float* __restrict__ b2,
                                                     float* __restrict__ out) {
    const int e   = blockIdx.z;
    const int cnt = g_count[e];
    const int m0  = blockIdx.y * TM;
    if (m0 >= cnt) return;
    const int n0  = blockIdx.x * TN;

    SMEM_DECL
    const int tid  = threadIdx.x;
    const int lane = tid & 31;
    const int wid  = tid >> 5;
    const int wm   = wid >> 2;
    const int wn   = wid & 3;
    const int fr   = lane >> 2;
    const int fc   = (lane & 3) * 2;
    FRAG_ADDR_DECL

    const int rA0 = tid >> 2;
    const int cA0 = tid & 3;
    const int rA1 = rA0 + 64;
    const int sOffA0 = rA0 * RS + cA0 * 8;
    const int sOffA1 = rA1 * RS + cA0 * 8;
    const int sOffB  = sOffA0;

    const int gb = g_base[e];
    const size_t aOff0 = (size_t)(gb + m0 + rA0) * DFF + cA0 * 8;
    const size_t aOff1 = (size_t)(gb + m0 + rA1) * DFF + cA0 * 8;
    const size_t bOff  = (size_t)(e * C_DIM + n0 + rA0) * DFF + cA0 * 8;

    float acc[4][2][4];
#pragma unroll
    for (int a = 0; a < 4; a++)
#pragma unroll
        for (int b = 0; b < 2; b++)
#pragma unroll
            for (int c = 0; c < 4; c++) acc[a][b][c] = 0.f;

    uint4 pah0, pah1, pal0, pal1, pbh, pbl;
#define G2_LOAD(K0)                                                   \
    pah0 = *(const uint4*)(g_hhi + aOff0 + (K0));                     \
    pah1 = *(const uint4*)(g_hhi + aOff1 + (K0));                     \
    pal0 = *(const uint4*)(g_hlo + aOff0 + (K0));                     \
    pal1 = *(const uint4*)(g_hlo + aOff1 + (K0));                     \
    pbh  = *(const uint4*)(g_w2hi + bOff + (K0));                     \
    pbl  = *(const uint4*)(g_w2lo + bOff + (K0));

    G2_LOAD(0);
    const int NK = DFF / KC;   // 48
    for (int kci = 0; kci < NK; kci++) {
        STORE_CHUNK();
        __syncthreads();
        if (kci + 1 < NK) { G2_LOAD((kci + 1) * KC); }
        FRAG_MMA_BLOCK();
        __syncthreads();
    }
#undef G2_LOAD

    const int c0 = wn * 16 + fc;
    const float* b2p = b2 + (size_t)e * C_DIM + n0;
    float2 bj0 = *(const float2*)(b2p + c0);
    float2 bj1 = *(const float2*)(b2p + c0 + 8);
#pragma unroll
    for (int mt = 0; mt < 4; mt++) {
#pragma unroll
        for (int hf = 0; hf < 2; hf++) {
            const int r = wm * 64 + mt * 16 + fr + hf * 8;
            const int p = m0 + r;
            if (p < cnt) {
                const int tok  = g_tok[e * CAP + p];
                const float gt = g_gslot[e * CAP + p];
                float* op = out + (size_t)tok * C_DIM + n0 + c0;
                float2 v0, v1;
                v0.x = (acc[mt][0][hf * 2]     + bj0.x) * gt;
                v0.y = (acc[mt][0][hf * 2 + 1] + bj0.y) * gt;
                v1.x = (acc[mt][1][hf * 2]     + bj1.x) * gt;
                v1.y = (acc[mt][1][hf * 2 + 1] + bj1.y) * gt;
                *(float2*)op       = v0;
                *(float2*)(op + 8) = v1;
            }
        }
    }
}

// ---------------------------- launch ----------------------------
extern "C" void kernel_launch(void* const* d_in, const int* in_sizes, int n_in,
                              void* d_out, int out_size) {
    const float* x       = (const float*)d_in[0];
    const float* noise   = (const float*)d_in[1];
    const float* w_route = (const float*)d_in[2];
    const float* b_route = (const float*)d_in[3];
    const float* w_noise = (const float*)d_in[4];
    const float* b_noise = (const float*)d_in[5];
    const float* w1      = (const float*)d_in[6];
    const float* b1      = (const float*)d_in[7];
    const float* w2      = (const float*)d_in[8];
    const float* b2      = (const float*)d_in[9];
    float* out = (float*)d_out;

    const int n4 = NTOK * C_DIM / 4;
    kzero<<<(n4 + 255) / 256, 256>>>((float4*)out, n4);
    kconv_x<<<(NTOK * C_DIM / 2 + 255) / 256, 256>>>((const float2*)x);
    ktrans<<<dim3(DFF / 32, C_DIM / 32, E_NUM), dim3(32, 8)>>>(w1, 0, C_DIM, DFF);
    ktrans<<<dim3(C_DIM / 32, DFF / 32, E_NUM), dim3(32, 8)>>>(w2, 1, DFF, C_DIM);
    kroute<<<NTOK / 8, 256>>>(x, noise, w_route, b_route, w_noise, b_noise);
    kscatter<<<1, 256>>>();
    kgemm1_mma<<<dim3(DFF / TN, CAP / TM, E_NUM), 256>>>(b1);
    kgemm2_mma<<<dim3(C_DIM / TN, CAP / TM, E_NUM), 256>>>(b2, out);
}

// round 8
// speedup vs baseline: 1.6235x; 1.0213x over previous
#include <cuda_runtime.h>
#include <cuda_bf16.h>
#include <math.h>
#include <stdint.h>

#define NTOK   32768
#define C_DIM  384
#define E_NUM  8
#define DFF    1536
#define CAP    8192
#define TM     128
#define TN     64
#define KC     32            // bf16 K elems per chunk
#define RS     40            // smem row stride in halfs (80B) -> conflict-free

#define STAGE_A (TM * RS)    // halfs per A-plane stage
#define STAGE_B (TN * RS)    // halfs per B-plane stage
// dynamic smem layout (bytes)
#define OFF_AH  0
#define OFF_AL  (2 * STAGE_A * 2)
#define OFF_BH  (4 * STAGE_A * 2)
#define OFF_BL  (4 * STAGE_A * 2 + 2 * STAGE_B * 2)
#define SMEM_TOT (4 * STAGE_A * 2 + 4 * STAGE_B * 2)   // 61440

// ---------------- persistent device scratch ----------------
__device__ int   g_texp[NTOK];
__device__ float g_tgate[NTOK];
__device__ int   g_tok[E_NUM * CAP];
__device__ float g_gslot[E_NUM * CAP];
__device__ int   g_count[E_NUM];
__device__ int   g_base[E_NUM];
__device__ __nv_bfloat16 g_xhi[(size_t)NTOK * C_DIM];
__device__ __nv_bfloat16 g_xlo[(size_t)NTOK * C_DIM];
__device__ __nv_bfloat16 g_w1hi[(size_t)E_NUM * DFF * C_DIM];   // [e][n=dff][k=c]
__device__ __nv_bfloat16 g_w1lo[(size_t)E_NUM * DFF * C_DIM];
__device__ __nv_bfloat16 g_w2hi[(size_t)E_NUM * C_DIM * DFF];   // [e][n=c][k=dff]
__device__ __nv_bfloat16 g_w2lo[(size_t)E_NUM * C_DIM * DFF];
__device__ __nv_bfloat16 g_hhi[(size_t)(NTOK + TM) * DFF];      // H hi plane (padded)
__device__ __nv_bfloat16 g_hlo[(size_t)(NTOK + TM) * DFF];

__device__ __forceinline__ uint32_t smem_to_u32(const void* p) {
    uint32_t a;
    asm("{ .reg .u64 t; cvta.to.shared.u64 t, %1; cvt.u32.u64 %0, t; }" : "=r"(a) : "l"(p));
    return a;
}

#define LDSM_X4(R0, R1, R2, R3, ADDR)                                             \
    asm volatile("ldmatrix.sync.aligned.m8n8.x4.shared.b16 {%0,%1,%2,%3}, [%4];"  \
                 : "=r"(R0), "=r"(R1), "=r"(R2), "=r"(R3) : "r"(ADDR))

#define MMA_BF16(D, A0, A1, A2, A3, B0, B1)                                       \
    asm volatile("mma.sync.aligned.m16n8k16.row.col.f32.bf16.bf16.f32 "           \
                 "{%0,%1,%2,%3}, {%4,%5,%6,%7}, {%8,%9}, {%0,%1,%2,%3};"          \
                 : "+f"((D)[0]), "+f"((D)[1]), "+f"((D)[2]), "+f"((D)[3])         \
                 : "r"(A0), "r"(A1), "r"(A2), "r"(A3), "r"(B0), "r"(B1))

// ---------------------------- zero output ----------------------------
__global__ __launch_bounds__(256) void kzero(float4* __restrict__ out, int n4) {
    int i = blockIdx.x * blockDim.x + threadIdx.x;
    if (i < n4) out[i] = make_float4(0.f, 0.f, 0.f, 0.f);
}

// ------------------- x -> bf16 hi/lo planes -------------------
__global__ __launch_bounds__(256) void kconv_x(const float2* __restrict__ x2) {
    int i = blockIdx.x * blockDim.x + threadIdx.x;
    float2 v = x2[i];
    __nv_bfloat16 h0 = __float2bfloat16(v.x);
    __nv_bfloat16 h1 = __float2bfloat16(v.y);
    __nv_bfloat16 l0 = __float2bfloat16(v.x - __bfloat162float(h0));
    __nv_bfloat16 l1 = __float2bfloat16(v.y - __bfloat162float(h1));
    ((__nv_bfloat162*)g_xhi)[i] = __nv_bfloat162(h0, h1);
    ((__nv_bfloat162*)g_xlo)[i] = __nv_bfloat162(l0, l1);
}

// ---- transpose + split: in [e][R][C] fp32 -> symbol planes [e][C][R] bf16 ----
__global__ __launch_bounds__(256) void ktrans(const float* __restrict__ in,
                                              int which, int R, int C) {
    __nv_bfloat16* __restrict__ ohi = which ? g_w2hi : g_w1hi;
    __nv_bfloat16* __restrict__ olo = which ? g_w2lo : g_w1lo;
    __shared__ float tile[32][33];
    const int bx = blockIdx.x, by = blockIdx.y, e = blockIdx.z;
    const int tx = threadIdx.x, ty = threadIdx.y;   // 32 x 8
    const float* ip = in + (size_t)e * R * C;
#pragma unroll
    for (int i = 0; i < 4; i++)
        tile[ty + 8 * i][tx] = ip[(size_t)(by * 32 + ty + 8 * i) * C + bx * 32 + tx];
    __syncthreads();
    const size_t op = (size_t)e * R * C;
#pragma unroll
    for (int i = 0; i < 4; i++) {
        float v = tile[tx][ty + 8 * i];
        __nv_bfloat16 h = __float2bfloat16(v);
        __nv_bfloat16 l = __float2bfloat16(v - __bfloat162float(h));
        size_t idx = op + (size_t)(bx * 32 + ty + 8 * i) * R + by * 32 + tx;
        ohi[idx] = h;
        olo[idx] = l;
    }
}

// ---------------------------- routing ----------------------------
__global__ __launch_bounds__(256) void kroute(
        const float* __restrict__ x, const float* __restrict__ noise,
        const float* __restrict__ w_route, const float* __restrict__ b_route,
        const float* __restrict__ w_noise, const float* __restrict__ b_noise) {
    __shared__ float swr[E_NUM * C_DIM];
    __shared__ float swn[E_NUM * C_DIM];
    for (int i = threadIdx.x; i < E_NUM * C_DIM; i += blockDim.x) {
        int c = i >> 3, e = i & 7;
        swr[e * C_DIM + c] = w_route[i];
        swn[e * C_DIM + c] = w_noise[i];
    }
    __syncthreads();
    const int lane = threadIdx.x & 31;
    const int warp = threadIdx.x >> 5;
    const int t = blockIdx.x * 8 + warp;

    float ar[E_NUM], an[E_NUM];
#pragma unroll
    for (int e = 0; e < E_NUM; e++) { ar[e] = 0.f; an[e] = 0.f; }
    const float* xr = x + (size_t)t * C_DIM;
#pragma unroll
    for (int j = 0; j < C_DIM / 32; j++) {
        const int c = j * 32 + lane;
        const float xv = xr[c];
#pragma unroll
        for (int e = 0; e < E_NUM; e++) {
            ar[e] = fmaf(xv, swr[e * C_DIM + c], ar[e]);
            an[e] = fmaf(xv, swn[e * C_DIM + c], an[e]);
        }
    }
#pragma unroll
    for (int e = 0; e < E_NUM; e++) {
#pragma unroll
        for (int off = 16; off > 0; off >>= 1) {
            ar[e] += __shfl_xor_sync(0xffffffffu, ar[e], off);
            an[e] += __shfl_xor_sync(0xffffffffu, an[e], off);
        }
    }
    if (lane == 0) {
        float ns[E_NUM];
        float best = -INFINITY; int bi = 0;
#pragma unroll
        for (int e = 0; e < E_NUM; e++) {
            float lg = ar[e] + b_route[e];
            float z  = an[e] + b_noise[e];
            float sp = fmaxf(z, 0.f) + log1pf(expf(-fabsf(z)));
            ns[e] = lg + noise[(size_t)t * E_NUM + e] * sp;
            if (ns[e] > best) { best = ns[e]; bi = e; }
        }
        float second = -INFINITY;
#pragma unroll
        for (int e = 0; e < E_NUM; e++)
            if (e != bi && ns[e] > second) second = ns[e];
        g_texp[t]  = bi;
        g_tgate[t] = 1.f / (1.f + expf(second - best));
    }
}

// ------------------ ordered compaction (single block, 256 thr) ------------------
__global__ __launch_bounds__(256) void kscatter() {
    __shared__ int s[E_NUM][256];
    __shared__ int stot[E_NUM];
    const int tid = threadIdx.x;
    const int CH  = NTOK / 256;
    const int t0  = tid * CH;

    int cnt[E_NUM];
#pragma unroll
    for (int e = 0; e < E_NUM; e++) cnt[e] = 0;
    for (int i = 0; i < CH; i++) cnt[g_texp[t0 + i]]++;
#pragma unroll
    for (int e = 0; e < E_NUM; e++) s[e][tid] = cnt[e];
    __syncthreads();
    for (int off = 1; off < 256; off <<= 1) {
        int v[E_NUM];
#pragma unroll
        for (int e = 0; e < E_NUM; e++) v[e] = (tid >= off) ? s[e][tid - off] : 0;
        __syncthreads();
#pragma unroll
        for (int e = 0; e < E_NUM; e++) s[e][tid] += v[e];
        __syncthreads();
    }
    int run[E_NUM];
#pragma unroll
    for (int e = 0; e < E_NUM; e++) run[e] = s[e][tid] - cnt[e];
    if (tid < E_NUM) stot[tid] = s[tid][255];
    __syncthreads();
    if (tid == 0) {
        int b = 0;
        for (int e = 0; e < E_NUM; e++) {
            int c = stot[e] < CAP ? stot[e] : CAP;
            g_count[e] = c;
            g_base[e]  = b;
            b += c;
        }
    }
    for (int i = 0; i < CH; i++) {
        int t = t0 + i;
        int e = g_texp[t];
        int p = run[e]++;
        if (p < CAP) {
            g_tok[e * CAP + p]   = t;
            g_gslot[e * CAP + p] = g_tgate[t];
        }
    }
}

// ========== ldmatrix fragment + mma block (one K-chunk, staged) ==========
#define FRAG_MMA_BLOCK(STA, STB)                                                  \
    _Pragma("unroll")                                                             \
    for (int ks = 0; ks < 2; ks++) {                                              \
        uint32_t bh[4], bl[4];                                                    \
        LDSM_X4(bh[0], bh[1], bh[2], bh[3], bBaseH + (STB) + ks * 32);            \
        LDSM_X4(bl[0], bl[1], bl[2], bl[3], bBaseL + (STB) + ks * 32);            \
        _Pragma("unroll")                                                         \
        for (int mt = 0; mt < 4; mt++) {                                          \
            uint32_t ah[4], al[4];                                                \
            LDSM_X4(ah[0], ah[1], ah[2], ah[3],                                   \
                    aBaseH + (STA) + mt * (16 * RS * 2) + ks * 32);               \
            LDSM_X4(al[0], al[1], al[2], al[3],                                   \
                    aBaseL + (STA) + mt * (16 * RS * 2) + ks * 32);               \
            _Pragma("unroll")                                                     \
            for (int j = 0; j < 2; j++) {                                         \
                MMA_BF16(acc[mt][j], ah[0], ah[1], ah[2], ah[3],                  \
                         bh[2 * j], bh[2 * j + 1]);                               \
                MMA_BF16(acc[mt][j], al[0], al[1], al[2], al[3],                  \
                         bh[2 * j], bh[2 * j + 1]);                               \
                MMA_BF16(acc[mt][j], ah[0], ah[1], ah[2], ah[3],                  \
                         bl[2 * j], bl[2 * j + 1]);                               \
            }                                                                     \
        }                                                                         \
    }

#define SMEM_DECL                                                                 \
    extern __shared__ __align__(16) char dsm[];                                   \
    __nv_bfloat16* const sAh = (__nv_bfloat16*)(dsm + OFF_AH);                    \
    __nv_bfloat16* const sAl = (__nv_bfloat16*)(dsm + OFF_AL);                    \
    __nv_bfloat16* const sBh = (__nv_bfloat16*)(dsm + OFF_BH);                    \
    __nv_bfloat16* const sBl = (__nv_bfloat16*)(dsm + OFF_BL);

#define FRAG_ADDR_DECL                                                            \
    const uint32_t aBaseH = smem_to_u32(sAh) +                                    \
        (uint32_t)(((wm * 64 + (lane & 15)) * RS + (lane >> 4) * 8) * 2);         \
    const uint32_t aBaseL = smem_to_u32(sAl) +                                    \
        (uint32_t)(((wm * 64 + (lane & 15)) * RS + (lane >> 4) * 8) * 2);         \
    const uint32_t bBaseH = smem_to_u32(sBh) +                                    \
        (uint32_t)(((wn * 16 + (lane & 7) + ((lane >> 4) & 1) * 8) * RS +         \
                    ((lane >> 3) & 1) * 8) * 2);                                  \
    const uint32_t bBaseL = smem_to_u32(sBl) +                                    \
        (uint32_t)(((wn * 16 + (lane & 7) + ((lane >> 4) & 1) * 8) * RS +         \
                    ((lane >> 3) & 1) * 8) * 2);

#define STORE_CHUNK(STA, STB)                                                     \
    *(uint4*)&sAh[(STA) + sOffA0] = pah0;                                         \
    *(uint4*)&sAh[(STA) + sOffA1] = pah1;                                         \
    *(uint4*)&sAl[(STA) + sOffA0] = pal0;                                         \
    *(uint4*)&sAl[(STA) + sOffA1] = pal1;                                         \
    *(uint4*)&sBh[(STB) + sOffB]  = pbh;                                          \
    *(uint4*)&sBl[(STB) + sOffB]  = pbl;

// ----------------- GEMM1: H = relu(Xg @ W1 + b1)^2 (bf16 split out) -----------------
__global__ __launch_bounds__(256, 2) void kgemm1_mma(const float* __restrict__ b1) {
    const int e   = blockIdx.z;
    const int cnt = g_count[e];
    const int m0  = blockIdx.y * TM;
    if (m0 >= cnt) return;
    const int n0  = blockIdx.x * TN;

    SMEM_DECL
    const int tid  = threadIdx.x;
    const int lane = tid & 31;
    const int wid  = tid >> 5;
    const int wm   = wid >> 2;          // 0..1
    const int wn   = wid & 3;           // 0..3
    const int fr   = lane >> 2;         // 0..7
    const int fc   = (lane & 3) * 2;    // 0,2,4,6
    FRAG_ADDR_DECL

    const int rA0 = tid >> 2;           // 0..63
    const int cA0 = tid & 3;            // chunk of 8 halfs
    const int rA1 = rA0 + 64;
    const int sOffA0 = rA0 * RS + cA0 * 8;
    const int sOffA1 = rA1 * RS + cA0 * 8;
    const int sOffB  = sOffA0;

    const int tk0 = g_tok[e * CAP + m0 + rA0];
    const int tk1 = g_tok[e * CAP + m0 + rA1];
    const size_t aOff0 = (size_t)tk0 * C_DIM + cA0 * 8;
    const size_t aOff1 = (size_t)tk1 * C_DIM + cA0 * 8;
    const size_t bOff  = (size_t)(e * DFF + n0 + rA0) * C_DIM + cA0 * 8;

    float acc[4][2][4];
#pragma unroll
    for (int a = 0; a < 4; a++)
#pragma unroll
        for (int b = 0; b < 2; b++)
#pragma unroll
            for (int c = 0; c < 4; c++) acc[a][b][c] = 0.f;

    uint4 pah0, pah1, pal0, pal1, pbh, pbl;
#define G1_LOAD(K0)                                                   \
    pah0 = *(const uint4*)(g_xhi + aOff0 + (K0));                     \
    pah1 = *(const uint4*)(g_xhi + aOff1 + (K0));                     \
    pal0 = *(const uint4*)(g_xlo + aOff0 + (K0));                     \
    pal1 = *(const uint4*)(g_xlo + aOff1 + (K0));                     \
    pbh  = *(const uint4*)(g_w1hi + bOff + (K0));                     \
    pbl  = *(const uint4*)(g_w1lo + bOff + (K0));

    G1_LOAD(0);
    STORE_CHUNK(0, 0);
    __syncthreads();
    const int NK = C_DIM / KC;   // 12
    for (int kci = 0; kci < NK; kci++) {
        const int cur = kci & 1;
        if (kci + 1 < NK) { G1_LOAD((kci + 1) * KC); }
        FRAG_MMA_BLOCK(cur * (STAGE_A * 2), cur * (STAGE_B * 2));
        if (kci + 1 < NK) {
            const int nxt = cur ^ 1;
            STORE_CHUNK(nxt * STAGE_A, nxt * STAGE_B);
        }
        __syncthreads();
    }
#undef G1_LOAD

    // epilogue: bias + relu^2 + hi/lo split -> g_hhi/g_hlo
    const int gb = g_base[e];
    const int c0 = wn * 16 + fc;
    const float* b1p = b1 + (size_t)e * DFF + n0;
    float2 bj0 = *(const float2*)(b1p + c0);
    float2 bj1 = *(const float2*)(b1p + c0 + 8);
#pragma unroll
    for (int mt = 0; mt < 4; mt++) {
#pragma unroll
        for (int hf = 0; hf < 2; hf++) {
            const int r = wm * 64 + mt * 16 + fr + hf * 8;
            const int p = m0 + r;
            if (p < cnt) {
                __nv_bfloat16* hh = g_hhi + (size_t)(gb + p) * DFF + n0;
                __nv_bfloat16* hl = g_hlo + (size_t)(gb + p) * DFF + n0;
#pragma unroll
                for (int j = 0; j < 2; j++) {
                    float v0 = acc[mt][j][hf * 2]     + (j ? bj1.x : bj0.x);
                    float v1 = acc[mt][j][hf * 2 + 1] + (j ? bj1.y : bj0.y);
                    v0 = fmaxf(v0, 0.f); v0 *= v0;
                    v1 = fmaxf(v1, 0.f); v1 *= v1;
                    __nv_bfloat16 h0 = __float2bfloat16(v0);
                    __nv_bfloat16 h1 = __float2bfloat16(v1);
                    __nv_bfloat16 l0 = __float2bfloat16(v0 - __bfloat162float(h0));
                    __nv_bfloat16 l1 = __float2bfloat16(v1 - __bfloat162float(h1));
                    *(__nv_bfloat162*)(hh + c0 + j * 8) = __nv_bfloat162(h0, h1);
                    *(__nv_bfloat162*)(hl + c0 + j * 8) = __nv_bfloat162(l0, l1);
                }
            }
        }
    }
}

// -------- GEMM2: out[tok] = gate * (H @ W2 + b2), scatter --------
__global__ __launch_bounds__(256, 2) void kgemm2_mma(const float* __restrict__ b2,
                                                     float* __restrict__ out) {
    const int e   = blockIdx.z;
    const int cnt = g_count[e];
    const int m0  = blockIdx.y * TM;
    if (m0 >= cnt) return;
    const int n0  = blockIdx.x * TN;

    SMEM_DECL
    const int tid  = threadIdx.x;
    const int lane = tid & 31;
    const int wid  = tid >> 5;
    const int wm   = wid >> 2;
    const int wn   = wid & 3;
    const int fr   = lane >> 2;
    const int fc   = (lane & 3) * 2;
    FRAG_ADDR_DECL

    const int rA0 = tid >> 2;
    const int cA0 = tid & 3;
    const int rA1 = rA0 + 64;
    const int sOffA0 = rA0 * RS + cA0 * 8;
    const int sOffA1 = rA1 * RS + cA0 * 8;
    const int sOffB  = sOffA0;

    const int gb = g_base[e];
    const size_t aOff0 = (size_t)(gb + m0 + rA0) * DFF + cA0 * 8;
    const size_t aOff1 = (size_t)(gb + m0 + rA1) * DFF + cA0 * 8;
    const size_t bOff  = (size_t)(e * C_DIM + n0 + rA0) * DFF + cA0 * 8;

    float acc[4][2][4];
#pragma unroll
    for (int a = 0; a < 4; a++)
#pragma unroll
        for (int b = 0; b < 2; b++)
#pragma unroll
            for (int c = 0; c < 4; c++) acc[a][b][c] = 0.f;

    uint4 pah0, pah1, pal0, pal1, pbh, pbl;
#define G2_LOAD(K0)                                                   \
    pah0 = *(const uint4*)(g_hhi + aOff0 + (K0));                     \
    pah1 = *(const uint4*)(g_hhi + aOff1 + (K0));                     \
    pal0 = *(const uint4*)(g_hlo + aOff0 + (K0));                     \
    pal1 = *(const uint4*)(g_hlo + aOff1 + (K0));                     \
    pbh  = *(const uint4*)(g_w2hi + bOff + (K0));                     \
    pbl  = *(const uint4*)(g_w2lo + bOff + (K0));

    G2_LOAD(0);
    STORE_CHUNK(0, 0);
    __syncthreads();
    const int NK = DFF / KC;   // 48
    for (int kci = 0; kci < NK; kci++) {
        const int cur = kci & 1;
        if (kci + 1 < NK) { G2_LOAD((kci + 1) * KC); }
        FRAG_MMA_BLOCK(cur * (STAGE_A * 2), cur * (STAGE_B * 2));
        if (kci + 1 < NK) {
            const int nxt = cur ^ 1;
            STORE_CHUNK(nxt * STAGE_A, nxt * STAGE_B);
        }
        __syncthreads();
    }
#undef G2_LOAD

    const int c0 = wn * 16 + fc;
    const float* b2p = b2 + (size_t)e * C_DIM + n0;
    float2 bj0 = *(const float2*)(b2p + c0);
    float2 bj1 = *(const float2*)(b2p + c0 + 8);
#pragma unroll
    for (int mt = 0; mt < 4; mt++) {
#pragma unroll
        for (int hf = 0; hf < 2; hf++) {
            const int r = wm * 64 + mt * 16 + fr + hf * 8;
            const int p = m0 + r;
            if (p < cnt) {
                const int tok  = g_tok[e * CAP + p];
                const float gt = g_gslot[e * CAP + p];
                float* op = out + (size_t)tok * C_DIM + n0 + c0;
                float2 v0, v1;
                v0.x = (acc[mt][0][hf * 2]     + bj0.x) * gt;
                v0.y = (acc[mt][0][hf * 2 + 1] + bj0.y) * gt;
                v1.x = (acc[mt][1][hf * 2]     + bj1.x) * gt;
                v1.y = (acc[mt][1][hf * 2 + 1] + bj1.y) * gt;
                *(float2*)op       = v0;
                *(float2*)(op + 8) = v1;
            }
        }
    }
}

// ---------------------------- launch ----------------------------
extern "C" void kernel_launch(void* const* d_in, const int* in_sizes, int n_in,
                              void* d_out, int out_size) {
    const float* x       = (const float*)d_in[0];
    const float* noise   = (const float*)d_in[1];
    const float* w_route = (const float*)d_in[2];
    const float* b_route = (const float*)d_in[3];
    const float* w_noise = (const float*)d_in[4];
    const float* b_noise = (const float*)d_in[5];
    const float* w1      = (const float*)d_in[6];
    const float* b1      = (const float*)d_in[7];
    const float* w2      = (const float*)d_in[8];
    const float* b2      = (const float*)d_in[9];
    float* out = (float*)d_out;

    cudaFuncSetAttribute(kgemm1_mma, cudaFuncAttributeMaxDynamicSharedMemorySize, SMEM_TOT);
    cudaFuncSetAttribute(kgemm2_mma, cudaFuncAttributeMaxDynamicSharedMemorySize, SMEM_TOT);

    const int n4 = NTOK * C_DIM / 4;
    kzero<<<(n4 + 255) / 256, 256>>>((float4*)out, n4);
    kconv_x<<<(NTOK * C_DIM / 2 + 255) / 256, 256>>>((const float2*)x);
    ktrans<<<dim3(DFF / 32, C_DIM / 32, E_NUM), dim3(32, 8)>>>(w1, 0, C_DIM, DFF);
    ktrans<<<dim3(C_DIM / 32, DFF / 32, E_NUM), dim3(32, 8)>>>(w2, 1, DFF, C_DIM);
    kroute<<<NTOK / 8, 256>>>(x, noise, w_route, b_route, w_noise, b_noise);
    kscatter<<<1, 256>>>();
    kgemm1_mma<<<dim3(DFF / TN, CAP / TM, E_NUM), 256, SMEM_TOT>>>(b1);
    kgemm2_mma<<<dim3(C_DIM / TN, CAP / TM, E_NUM), 256, SMEM_TOT>>>(b2, out);
}

// round 9
// speedup vs baseline: 1.9255x; 1.1860x over previous
#include <cuda_runtime.h>
#include <cuda_bf16.h>
#include <math.h>
#include <stdint.h>

#define NTOK   32768
#define C_DIM  384
#define E_NUM  8
#define DFF    1536
#define CAP    8192
#define TM     128
#define TN     128
#define KC     32            // bf16 K elems per chunk
#define RS     40            // smem row stride in halfs (80B) -> conflict-free

// dynamic smem: 4 plane regions (AH, AL, BH, BL), each 2 stages of 128*RS*2 = 10240 B
#define STG_B   10240
#define OFF_AH  0
#define OFF_AL  20480
#define OFF_BH  40960
#define OFF_BL  61440
#define SMEM_TOT 81920

// ---------------- persistent device scratch ----------------
__device__ int   g_texp[NTOK];
__device__ float g_tgate[NTOK];
__device__ int   g_tok[E_NUM * CAP];
__device__ float g_gslot[E_NUM * CAP];
__device__ int   g_count[E_NUM];
__device__ int   g_base[E_NUM];
__device__ __nv_bfloat16 g_xhi[(size_t)NTOK * C_DIM];
__device__ __nv_bfloat16 g_xlo[(size_t)NTOK * C_DIM];
__device__ __nv_bfloat16 g_w1hi[(size_t)E_NUM * DFF * C_DIM];   // [e][n=dff][k=c]
__device__ __nv_bfloat16 g_w1lo[(size_t)E_NUM * DFF * C_DIM];
__device__ __nv_bfloat16 g_w2hi[(size_t)E_NUM * C_DIM * DFF];   // [e][n=c][k=dff]
__device__ __nv_bfloat16 g_w2lo[(size_t)E_NUM * C_DIM * DFF];
__device__ __nv_bfloat16 g_hhi[(size_t)(NTOK + TM) * DFF];      // H hi plane (padded)
__device__ __nv_bfloat16 g_hlo[(size_t)(NTOK + TM) * DFF];

__device__ __forceinline__ uint32_t smem_to_u32(const void* p) {
    uint32_t a;
    asm("{ .reg .u64 t; cvta.to.shared.u64 t, %1; cvt.u32.u64 %0, t; }" : "=r"(a) : "l"(p));
    return a;
}

#define LDSM_X4(R0, R1, R2, R3, ADDR)                                             \
    asm volatile("ldmatrix.sync.aligned.m8n8.x4.shared.b16 {%0,%1,%2,%3}, [%4];"  \
                 : "=r"(R0), "=r"(R1), "=r"(R2), "=r"(R3) : "r"(ADDR))

#define MMA_BF16(D, A0, A1, A2, A3, B0, B1)                                       \
    asm volatile("mma.sync.aligned.m16n8k16.row.col.f32.bf16.bf16.f32 "           \
                 "{%0,%1,%2,%3}, {%4,%5,%6,%7}, {%8,%9}, {%0,%1,%2,%3};"          \
                 : "+f"((D)[0]), "+f"((D)[1]), "+f"((D)[2]), "+f"((D)[3])         \
                 : "r"(A0), "r"(A1), "r"(A2), "r"(A3), "r"(B0), "r"(B1))

#define CP16(SADDR, GPTR)                                                         \
    asm volatile("cp.async.cg.shared.global [%0], [%1], 16;"                      \
                 :: "r"((uint32_t)(SADDR)), "l"(GPTR) : "memory")
#define CP_COMMIT() asm volatile("cp.async.commit_group;" ::: "memory")
#define CP_WAIT0()  asm volatile("cp.async.wait_group 0;" ::: "memory")

// -------------- x -> bf16 hi/lo planes + zero output --------------
__global__ __launch_bounds__(256) void kconv_x(const float2* __restrict__ x2,
                                               float2* __restrict__ out2) {
    int i = blockIdx.x * blockDim.x + threadIdx.x;
    float2 v = x2[i];
    __nv_bfloat16 h0 = __float2bfloat16(v.x);
    __nv_bfloat16 h1 = __float2bfloat16(v.y);
    __nv_bfloat16 l0 = __float2bfloat16(v.x - __bfloat162float(h0));
    __nv_bfloat16 l1 = __float2bfloat16(v.y - __bfloat162float(h1));
    ((__nv_bfloat162*)g_xhi)[i] = __nv_bfloat162(h0, h1);
    ((__nv_bfloat162*)g_xlo)[i] = __nv_bfloat162(l0, l1);
    out2[i] = make_float2(0.f, 0.f);
}

// ---- transpose + split: in [e][R][C] fp32 -> symbol planes [e][C][R] bf16 ----
__global__ __launch_bounds__(256) void ktrans(const float* __restrict__ in,
                                              int which, int R, int C) {
    __nv_bfloat16* __restrict__ ohi = which ? g_w2hi : g_w1hi;
    __nv_bfloat16* __restrict__ olo = which ? g_w2lo : g_w1lo;
    __shared__ float tile[32][33];
    const int bx = blockIdx.x, by = blockIdx.y, e = blockIdx.z;
    const int tx = threadIdx.x, ty = threadIdx.y;   // 32 x 8
    const float* ip = in + (size_t)e * R * C;
#pragma unroll
    for (int i = 0; i < 4; i++)
        tile[ty + 8 * i][tx] = ip[(size_t)(by * 32 + ty + 8 * i) * C + bx * 32 + tx];
    __syncthreads();
    const size_t op = (size_t)e * R * C;
#pragma unroll
    for (int i = 0; i < 4; i++) {
        float v = tile[tx][ty + 8 * i];
        __nv_bfloat16 h = __float2bfloat16(v);
        __nv_bfloat16 l = __float2bfloat16(v - __bfloat162float(h));
        size_t idx = op + (size_t)(bx * 32 + ty + 8 * i) * R + by * 32 + tx;
        ohi[idx] = h;
        olo[idx] = l;
    }
}

// ---------------------------- routing ----------------------------
__global__ __launch_bounds__(256) void kroute(
        const float* __restrict__ x, const float* __restrict__ noise,
        const float* __restrict__ w_route, const float* __restrict__ b_route,
        const float* __restrict__ w_noise, const float* __restrict__ b_noise) {
    __shared__ float swr[E_NUM * C_DIM];
    __shared__ float swn[E_NUM * C_DIM];
    for (int i = threadIdx.x; i < E_NUM * C_DIM; i += blockDim.x) {
        int c = i >> 3, e = i & 7;
        swr[e * C_DIM + c] = w_route[i];
        swn[e * C_DIM + c] = w_noise[i];
    }
    __syncthreads();
    const int lane = threadIdx.x & 31;
    const int warp = threadIdx.x >> 5;
    const int t = blockIdx.x * 8 + warp;

    float ar[E_NUM], an[E_NUM];
#pragma unroll
    for (int e = 0; e < E_NUM; e++) { ar[e] = 0.f; an[e] = 0.f; }
    const float* xr = x + (size_t)t * C_DIM;
#pragma unroll
    for (int j = 0; j < C_DIM / 32; j++) {
        const int c = j * 32 + lane;
        const float xv = xr[c];
#pragma unroll
        for (int e = 0; e < E_NUM; e++) {
            ar[e] = fmaf(xv, swr[e * C_DIM + c], ar[e]);
            an[e] = fmaf(xv, swn[e * C_DIM + c], an[e]);
        }
    }
#pragma unroll
    for (int e = 0; e < E_NUM; e++) {
#pragma unroll
        for (int off = 16; off > 0; off >>= 1) {
            ar[e] += __shfl_xor_sync(0xffffffffu, ar[e], off);
            an[e] += __shfl_xor_sync(0xffffffffu, an[e], off);
        }
    }
    if (lane == 0) {
        float ns[E_NUM];
        float best = -INFINITY; int bi = 0;
#pragma unroll
        for (int e = 0; e < E_NUM; e++) {
            float lg = ar[e] + b_route[e];
            float z  = an[e] + b_noise[e];
            float sp = fmaxf(z, 0.f) + log1pf(expf(-fabsf(z)));
            ns[e] = lg + noise[(size_t)t * E_NUM + e] * sp;
            if (ns[e] > best) { best = ns[e]; bi = e; }
        }
        float second = -INFINITY;
#pragma unroll
        for (int e = 0; e < E_NUM; e++)
            if (e != bi && ns[e] > second) second = ns[e];
        g_texp[t]  = bi;
        g_tgate[t] = 1.f / (1.f + expf(second - best));
    }
}

// ------------------ ordered compaction (single block, 256 thr) ------------------
__global__ __launch_bounds__(256) void kscatter() {
    __shared__ int s[E_NUM][256];
    __shared__ int stot[E_NUM];
    const int tid = threadIdx.x;
    const int CH  = NTOK / 256;
    const int t0  = tid * CH;

    int cnt[E_NUM];
#pragma unroll
    for (int e = 0; e < E_NUM; e++) cnt[e] = 0;
    for (int i = 0; i < CH; i++) cnt[g_texp[t0 + i]]++;
#pragma unroll
    for (int e = 0; e < E_NUM; e++) s[e][tid] = cnt[e];
    __syncthreads();
    for (int off = 1; off < 256; off <<= 1) {
        int v[E_NUM];
#pragma unroll
        for (int e = 0; e < E_NUM; e++) v[e] = (tid >= off) ? s[e][tid - off] : 0;
        __syncthreads();
#pragma unroll
        for (int e = 0; e < E_NUM; e++) s[e][tid] += v[e];
        __syncthreads();
    }
    int run[E_NUM];
#pragma unroll
    for (int e = 0; e < E_NUM; e++) run[e] = s[e][tid] - cnt[e];
    if (tid < E_NUM) stot[tid] = s[tid][255];
    __syncthreads();
    if (tid == 0) {
        int b = 0;
        for (int e = 0; e < E_NUM; e++) {
            int c = stot[e] < CAP ? stot[e] : CAP;
            g_count[e] = c;
            g_base[e]  = b;
            b += c;
        }
    }
    for (int i = 0; i < CH; i++) {
        int t = t0 + i;
        int e = g_texp[t];
        int p = run[e]++;
        if (p < CAP) {
            g_tok[e * CAP + p]   = t;
            g_gslot[e * CAP + p] = g_tgate[t];
        }
    }
}

// ========== ldmatrix fragment + mma block (one K-chunk, stage byte off ST) ==========
// warp tile: m = wm*64 + mt*16 (mt 0..3), n = wn*32 + j*8 (j 0..3)
#define FRAG_MMA_BLOCK(ST)                                                        \
    _Pragma("unroll")                                                             \
    for (int ks = 0; ks < 2; ks++) {                                              \
        uint32_t bh[8], bl[8];                                                    \
        LDSM_X4(bh[0], bh[1], bh[2], bh[3], bBaseH + (ST) + ks * 32);             \
        LDSM_X4(bh[4], bh[5], bh[6], bh[7], bBaseH + (ST) + 1280 + ks * 32);      \
        LDSM_X4(bl[0], bl[1], bl[2], bl[3], bBaseL + (ST) + ks * 32);             \
        LDSM_X4(bl[4], bl[5], bl[6], bl[7], bBaseL + (ST) + 1280 + ks * 32);      \
        _Pragma("unroll")                                                         \
        for (int mt = 0; mt < 4; mt++) {                                          \
            uint32_t ah[4], al[4];                                                \
            LDSM_X4(ah[0], ah[1], ah[2], ah[3],                                   \
                    aBaseH + (ST) + mt * (16 * RS * 2) + ks * 32);                \
            LDSM_X4(al[0], al[1], al[2], al[3],                                   \
                    aBaseL + (ST) + mt * (16 * RS * 2) + ks * 32);                \
            _Pragma("unroll")                                                     \
            for (int j = 0; j < 4; j++) {                                         \
                MMA_BF16(acc[mt][j], ah[0], ah[1], ah[2], ah[3],                  \
                         bh[2 * j], bh[2 * j + 1]);                               \
                MMA_BF16(acc[mt][j], al[0], al[1], al[2], al[3],                  \
                         bh[2 * j], bh[2 * j + 1]);                               \
                MMA_BF16(acc[mt][j], ah[0], ah[1], ah[2], ah[3],                  \
                         bl[2 * j], bl[2 * j + 1]);                               \
            }                                                                     \
        }                                                                         \
    }

#define SMEM_DECL extern __shared__ __align__(16) char dsm[];                     \
    const uint32_t sb = smem_to_u32(dsm);

#define FRAG_ADDR_DECL                                                            \
    const uint32_t aBaseH = sb + OFF_AH +                                         \
        (uint32_t)(((wm * 64 + (lane & 15)) * RS + (lane >> 4) * 8) * 2);         \
    const uint32_t aBaseL = sb + OFF_AL +                                         \
        (uint32_t)(((wm * 64 + (lane & 15)) * RS + (lane >> 4) * 8) * 2);         \
    const uint32_t bBaseH = sb + OFF_BH +                                         \
        (uint32_t)(((wn * 32 + (lane & 7) + ((lane >> 4) & 1) * 8) * RS +         \
                    ((lane >> 3) & 1) * 8) * 2);                                  \
    const uint32_t bBaseL = sb + OFF_BL +                                         \
        (uint32_t)(((wn * 32 + (lane & 7) + ((lane >> 4) & 1) * 8) * RS +         \
                    ((lane >> 3) & 1) * 8) * 2);

// per-thread staging map: assignments i = tid, tid+256; row = i>>2, 16B chunk = i&3
#define STAGE_IDX_DECL                                                            \
    const int rowS0 = tid >> 2,        chS0 = tid & 3;                            \
    const int rowS1 = (tid + 256) >> 2, chS1 = (tid + 256) & 3;                   \
    const uint32_t sOff0 = (uint32_t)(rowS0 * 80 + chS0 * 16);                    \
    const uint32_t sOff1 = (uint32_t)(rowS1 * 80 + chS1 * 16);

// ----------------- GEMM1: H = relu(Xg @ W1 + b1)^2 (bf16 split out) -----------------
__global__ __launch_bounds__(256, 2) void kgemm1_mma(const float* __restrict__ b1) {
    const int e   = blockIdx.z;
    const int cnt = g_count[e];
    const int m0  = blockIdx.y * TM;
    if (m0 >= cnt) return;
    const int n0  = blockIdx.x * TN;

    SMEM_DECL
    const int tid  = threadIdx.x;
    const int lane = tid & 31;
    const int wid  = tid >> 5;
    const int wm   = wid >> 2;          // 0..1
    const int wn   = wid & 3;           // 0..3
    const int fr   = lane >> 2;         // 0..7
    const int fc   = (lane & 3) * 2;    // 0,2,4,6
    FRAG_ADDR_DECL
    STAGE_IDX_DECL

    const int tk0 = g_tok[e * CAP + m0 + rowS0];
    const int tk1 = g_tok[e * CAP + m0 + rowS1];
    const size_t aG0 = (size_t)tk0 * C_DIM + chS0 * 8;
    const size_t aG1 = (size_t)tk1 * C_DIM + chS1 * 8;
    const size_t bG0 = (size_t)(e * DFF + n0 + rowS0) * C_DIM + chS0 * 8;
    const size_t bG1 = (size_t)(e * DFF + n0 + rowS1) * C_DIM + chS1 * 8;

    float acc[4][4][4];
#pragma unroll
    for (int a = 0; a < 4; a++)
#pragma unroll
        for (int b = 0; b < 4; b++)
#pragma unroll
            for (int c = 0; c < 4; c++) acc[a][b][c] = 0.f;

#define G1_ISSUE(K0, ST)                                                          \
    CP16(sb + OFF_AH + (ST) + sOff0, g_xhi + aG0 + (K0));                         \
    CP16(sb + OFF_AH + (ST) + sOff1, g_xhi + aG1 + (K0));                         \
    CP16(sb + OFF_AL + (ST) + sOff0, g_xlo + aG0 + (K0));                         \
    CP16(sb + OFF_AL + (ST) + sOff1, g_xlo + aG1 + (K0));                         \
    CP16(sb + OFF_BH + (ST) + sOff0, g_w1hi + bG0 + (K0));                        \
    CP16(sb + OFF_BH + (ST) + sOff1, g_w1hi + bG1 + (K0));                        \
    CP16(sb + OFF_BL + (ST) + sOff0, g_w1lo + bG0 + (K0));                        \
    CP16(sb + OFF_BL + (ST) + sOff1, g_w1lo + bG1 + (K0));                        \
    CP_COMMIT();

    G1_ISSUE(0, 0);
    const int NK = C_DIM / KC;   // 12
    for (int kci = 0; kci < NK; kci++) {
        CP_WAIT0();
        __syncthreads();
        const uint32_t st = (uint32_t)(kci & 1) * STG_B;
        if (kci + 1 < NK) { G1_ISSUE((kci + 1) * KC, st ^ STG_B); }
        FRAG_MMA_BLOCK(st);
    }
#undef G1_ISSUE

    // epilogue: bias + relu^2 + hi/lo split -> g_hhi/g_hlo
    const int gb = g_base[e];
    const int c0 = wn * 32 + fc;
    const float* b1p = b1 + (size_t)e * DFF + n0;
    float2 bj[4];
#pragma unroll
    for (int j = 0; j < 4; j++) bj[j] = *(const float2*)(b1p + c0 + j * 8);
#pragma unroll
    for (int mt = 0; mt < 4; mt++) {
#pragma unroll
        for (int hf = 0; hf < 2; hf++) {
            const int r = wm * 64 + mt * 16 + fr + hf * 8;
            const int p = m0 + r;
            if (p < cnt) {
                __nv_bfloat16* hh = g_hhi + (size_t)(gb + p) * DFF + n0;
                __nv_bfloat16* hl = g_hlo + (size_t)(gb + p) * DFF + n0;
#pragma unroll
                for (int j = 0; j < 4; j++) {
                    float v0 = acc[mt][j][hf * 2]     + bj[j].x;
                    float v1 = acc[mt][j][hf * 2 + 1] + bj[j].y;
                    v0 = fmaxf(v0, 0.f); v0 *= v0;
                    v1 = fmaxf(v1, 0.f); v1 *= v1;
                    __nv_bfloat16 h0 = __float2bfloat16(v0);
                    __nv_bfloat16 h1 = __float2bfloat16(v1);
                    __nv_bfloat16 l0 = __float2bfloat16(v0 - __bfloat162float(h0));
                    __nv_bfloat16 l1 = __float2bfloat16(v1 - __bfloat162float(h1));
                    *(__nv_bfloat162*)(hh + c0 + j * 8) = __nv_bfloat162(h0, h1);
                    *(__nv_bfloat162*)(hl + c0 + j * 8) = __nv_bfloat162(l0, l1);
                }
            }
        }
    }
}

// -------- GEMM2: out[tok] = gate * (H @ W2 + b2), scatter --------
__global__ __launch_bounds__(256, 2) void kgemm2_mma(const float* __restrict__ b2,
                                                     float* __restrict__ out) {
    const int e   = blockIdx.z;
    const int cnt = g_count[e];
    const int m0  = blockIdx.y * TM;
    if (m0 >= cnt) return;
    const int n0  = blockIdx.x * TN;

    SMEM_DECL
    const int tid  = threadIdx.x;
    const int lane = tid & 31;
    const int wid  = tid >> 5;
    const int wm   = wid >> 2;
    const int wn   = wid & 3;
    const int fr   = lane >> 2;
    const int fc   = (lane & 3) * 2;
    FRAG_ADDR_DECL
    STAGE_IDX_DECL

    const int gb = g_base[e];
    const size_t aG0 = (size_t)(gb + m0 + rowS0) * DFF + chS0 * 8;
    const size_t aG1 = (size_t)(gb + m0 + rowS1) * DFF + chS1 * 8;
    const size_t bG0 = (size_t)(e * C_DIM + n0 + rowS0) * DFF + chS0 * 8;
    const size_t bG1 = (size_t)(e * C_DIM + n0 + rowS1) * DFF + chS1 * 8;

    float acc[4][4][4];
#pragma unroll
    for (int a = 0; a < 4; a++)
#pragma unroll
        for (int b = 0; b < 4; b++)
#pragma unroll
            for (int c = 0; c < 4; c++) acc[a][b][c] = 0.f;

#define G2_ISSUE(K0, ST)                                                          \
    CP16(sb + OFF_AH + (ST) + sOff0, g_hhi + aG0 + (K0));                         \
    CP16(sb + OFF_AH + (ST) + sOff1, g_hhi + aG1 + (K0));                         \
    CP16(sb + OFF_AL + (ST) + sOff0, g_hlo + aG0 + (K0));                         \
    CP16(sb + OFF_AL + (ST) + sOff1, g_hlo + aG1 + (K0));                         \
    CP16(sb + OFF_BH + (ST) + sOff0, g_w2hi + bG0 + (K0));                        \
    CP16(sb + OFF_BH + (ST) + sOff1, g_w2hi + bG1 + (K0));                        \
    CP16(sb + OFF_BL + (ST) + sOff0, g_w2lo + bG0 + (K0));                        \
    CP16(sb + OFF_BL + (ST) + sOff1, g_w2lo + bG1 + (K0));                        \
    CP_COMMIT();

    G2_ISSUE(0, 0);
    const int NK = DFF / KC;   // 48
    for (int kci = 0; kci < NK; kci++) {
        CP_WAIT0();
        __syncthreads();
        const uint32_t st = (uint32_t)(kci & 1) * STG_B;
        if (kci + 1 < NK) { G2_ISSUE((kci + 1) * KC, st ^ STG_B); }
        FRAG_MMA_BLOCK(st);
    }
#undef G2_ISSUE

    const int c0 = wn * 32 + fc;
    const float* b2p = b2 + (size_t)e * C_DIM + n0;
    float2 bj[4];
#pragma unroll
    for (int j = 0; j < 4; j++) bj[j] = *(const float2*)(b2p + c0 + j * 8);
#pragma unroll
    for (int mt = 0; mt < 4; mt++) {
#pragma unroll
        for (int hf = 0; hf < 2; hf++) {
            const int r = wm * 64 + mt * 16 + fr + hf * 8;
            const int p = m0 + r;
            if (p < cnt) {
                const int tok  = g_tok[e * CAP + p];
                const float gt = g_gslot[e * CAP + p];
                float* op = out + (size_t)tok * C_DIM + n0 + c0;
#pragma unroll
                for (int j = 0; j < 4; j++) {
                    float2 v;
                    v.x = (acc[mt][j][hf * 2]     + bj[j].x) * gt;
                    v.y = (acc[mt][j][hf * 2 + 1] + bj[j].y) * gt;
                    *(float2*)(op + j * 8) = v;
                }
            }
        }
    }
}

// ---------------------------- launch ----------------------------
extern "C" void kernel_launch(void* const* d_in, const int* in_sizes, int n_in,
                              void* d_out, int out_size) {
    const float* x       = (const float*)d_in[0];
    const float* noise   = (const float*)d_in[1];
    const float* w_route = (const float*)d_in[2];
    const float* b_route = (const float*)d_in[3];
    const float* w_noise = (const float*)d_in[4];
    const float* b_noise = (const float*)d_in[5];
    const float* w1      = (const float*)d_in[6];
    const float* b1      = (const float*)d_in[7];
    const float* w2      = (const float*)d_in[8];
    const float* b2      = (const float*)d_in[9];
    float* out = (float*)d_out;

    cudaFuncSetAttribute(kgemm1_mma, cudaFuncAttributeMaxDynamicSharedMemorySize, SMEM_TOT);
    cudaFuncSetAttribute(kgemm2_mma, cudaFuncAttributeMaxDynamicSharedMemorySize, SMEM_TOT);

    kconv_x<<<NTOK * C_DIM / 2 / 256, 256>>>((const float2*)x, (float2*)out);
    ktrans<<<dim3(DFF / 32, C_DIM / 32, E_NUM), dim3(32, 8)>>>(w1, 0, C_DIM, DFF);
    ktrans<<<dim3(C_DIM / 32, DFF / 32, E_NUM), dim3(32, 8)>>>(w2, 1, DFF, C_DIM);
    kroute<<<NTOK / 8, 256>>>(x, noise, w_route, b_route, w_noise, b_noise);
    kscatter<<<1, 256>>>();
    kgemm1_mma<<<dim3(DFF / TN, CAP / TM, E_NUM), 256, SMEM_TOT>>>(b1);
    kgemm2_mma<<<dim3(C_DIM / TN, CAP / TM, E_NUM), 256, SMEM_TOT>>>(b2, out);
}

// round 10
// speedup vs baseline: 1.9764x; 1.0264x over previous
#include <cuda_runtime.h>
#include <cuda_bf16.h>
#include <math.h>
#include <stdint.h>

#define NTOK   32768
#define C_DIM  384
#define E_NUM  8
#define DFF    1536
#define CAP    8192
#define TM     128
#define TN     128
#define KC     32            // bf16 K elems per chunk
#define RS     40            // smem row stride in halfs (80B) -> conflict-free

// dynamic smem: 4 plane regions (AH, AL, BH, BL), each 2 stages of 128*RS*2 = 10240 B
#define STG_B   10240
#define OFF_AH  0
#define OFF_AL  20480
#define OFF_BH  40960
#define OFF_BL  61440
#define SMEM_TOT 81920

// ---------------- persistent device scratch ----------------
__device__ int   g_texp[NTOK];
__device__ float g_tgate[NTOK];
__device__ int   g_tok[E_NUM * CAP];
__device__ float g_gslot[E_NUM * CAP];
__device__ int   g_count[E_NUM];
__device__ int   g_base[E_NUM];
__device__ __nv_bfloat16 g_xhi[(size_t)NTOK * C_DIM];
__device__ __nv_bfloat16 g_xlo[(size_t)NTOK * C_DIM];
__device__ __nv_bfloat16 g_w1hi[(size_t)E_NUM * DFF * C_DIM];   // [e][n=dff][k=c]
__device__ __nv_bfloat16 g_w1lo[(size_t)E_NUM * DFF * C_DIM];
__device__ __nv_bfloat16 g_w2hi[(size_t)E_NUM * C_DIM * DFF];   // [e][n=c][k=dff]
__device__ __nv_bfloat16 g_w2lo[(size_t)E_NUM * C_DIM * DFF];
__device__ __nv_bfloat16 g_hhi[(size_t)(NTOK + TM) * DFF];      // H hi plane (padded)
__device__ __nv_bfloat16 g_hlo[(size_t)(NTOK + TM) * DFF];

__device__ __forceinline__ uint32_t smem_to_u32(const void* p) {
    uint32_t a;
    asm("{ .reg .u64 t; cvta.to.shared.u64 t, %1; cvt.u32.u64 %0, t; }" : "=r"(a) : "l"(p));
    return a;
}

#define LDSM_X4(R0, R1, R2, R3, ADDR)                                             \
    asm volatile("ldmatrix.sync.aligned.m8n8.x4.shared.b16 {%0,%1,%2,%3}, [%4];"  \
                 : "=r"(R0), "=r"(R1), "=r"(R2), "=r"(R3) : "r"(ADDR))

#define MMA_BF16(D, A0, A1, A2, A3, B0, B1)                                       \
    asm volatile("mma.sync.aligned.m16n8k16.row.col.f32.bf16.bf16.f32 "           \
                 "{%0,%1,%2,%3}, {%4,%5,%6,%7}, {%8,%9}, {%0,%1,%2,%3};"          \
                 : "+f"((D)[0]), "+f"((D)[1]), "+f"((D)[2]), "+f"((D)[3])         \
                 : "r"(A0), "r"(A1), "r"(A2), "r"(A3), "r"(B0), "r"(B1))

#define CP16(SADDR, GPTR)                                                         \
    asm volatile("cp.async.cg.shared.global [%0], [%1], 16;"                      \
                 :: "r"((uint32_t)(SADDR)), "l"(GPTR) : "memory")
#define CP_COMMIT() asm volatile("cp.async.commit_group;" ::: "memory")
#define CP_WAIT0()  asm volatile("cp.async.wait_group 0;" ::: "memory")

// -------------- x -> bf16 hi/lo planes + zero output --------------
__global__ __launch_bounds__(256) void kconv_x(const float2* __restrict__ x2,
                                               float2* __restrict__ out2) {
    int i = blockIdx.x * blockDim.x + threadIdx.x;
    float2 v = x2[i];
    __nv_bfloat16 h0 = __float2bfloat16(v.x);
    __nv_bfloat16 h1 = __float2bfloat16(v.y);
    __nv_bfloat16 l0 = __float2bfloat16(v.x - __bfloat162float(h0));
    __nv_bfloat16 l1 = __float2bfloat16(v.y - __bfloat162float(h1));
    ((__nv_bfloat162*)g_xhi)[i] = __nv_bfloat162(h0, h1);
    ((__nv_bfloat162*)g_xlo)[i] = __nv_bfloat162(l0, l1);
    out2[i] = make_float2(0.f, 0.f);
}

// ---- transpose + split: in [e][R][C] fp32 -> symbol planes [e][C][R] bf16 ----
__global__ __launch_bounds__(256) void ktrans(const float* __restrict__ in,
                                              int which, int R, int C) {
    __nv_bfloat16* __restrict__ ohi = which ? g_w2hi : g_w1hi;
    __nv_bfloat16* __restrict__ olo = which ? g_w2lo : g_w1lo;
    __shared__ float tile[32][33];
    const int bx = blockIdx.x, by = blockIdx.y, e = blockIdx.z;
    const int tx = threadIdx.x, ty = threadIdx.y;   // 32 x 8
    const float* ip = in + (size_t)e * R * C;
#pragma unroll
    for (int i = 0; i < 4; i++)
        tile[ty + 8 * i][tx] = ip[(size_t)(by * 32 + ty + 8 * i) * C + bx * 32 + tx];
    __syncthreads();
    const size_t op = (size_t)e * R * C;
#pragma unroll
    for (int i = 0; i < 4; i++) {
        float v = tile[tx][ty + 8 * i];
        __nv_bfloat16 h = __float2bfloat16(v);
        __nv_bfloat16 l = __float2bfloat16(v - __bfloat162float(h));
        size_t idx = op + (size_t)(bx * 32 + ty + 8 * i) * R + by * 32 + tx;
        ohi[idx] = h;
        olo[idx] = l;
    }
}

// ------------------- routing (vectorized float4) -------------------
__global__ __launch_bounds__(256) void kroute(
        const float* __restrict__ x, const float* __restrict__ noise,
        const float* __restrict__ w_route, const float* __restrict__ b_route,
        const float* __restrict__ w_noise, const float* __restrict__ b_noise) {
    __shared__ float swr[E_NUM * C_DIM];
    __shared__ float swn[E_NUM * C_DIM];
    for (int i = threadIdx.x; i < E_NUM * C_DIM; i += blockDim.x) {
        int c = i >> 3, e = i & 7;
        swr[e * C_DIM + c] = w_route[i];
        swn[e * C_DIM + c] = w_noise[i];
    }
    __syncthreads();
    const int lane = threadIdx.x & 31;
    const int warp = threadIdx.x >> 5;
    const int t = blockIdx.x * 8 + warp;

    float ar[E_NUM], an[E_NUM];
#pragma unroll
    for (int e = 0; e < E_NUM; e++) { ar[e] = 0.f; an[e] = 0.f; }
    const float4* xr4 = (const float4*)(x + (size_t)t * C_DIM);
#pragma unroll
    for (int j = 0; j < C_DIM / 128; j++) {           // 3 iters, float4 stride 32
        const int c4 = j * 32 + lane;                 // float4 index within row
        const float4 xv = xr4[c4];
#pragma unroll
        for (int e = 0; e < E_NUM; e++) {
            const float4 wr = *(const float4*)&swr[e * C_DIM + c4 * 4];
            const float4 wn = *(const float4*)&swn[e * C_DIM + c4 * 4];
            ar[e] = fmaf(xv.x, wr.x, fmaf(xv.y, wr.y, fmaf(xv.z, wr.z, fmaf(xv.w, wr.w, ar[e]))));
            an[e] = fmaf(xv.x, wn.x, fmaf(xv.y, wn.y, fmaf(xv.z, wn.z, fmaf(xv.w, wn.w, an[e]))));
        }
    }
#pragma unroll
    for (int e = 0; e < E_NUM; e++) {
#pragma unroll
        for (int off = 16; off > 0; off >>= 1) {
            ar[e] += __shfl_xor_sync(0xffffffffu, ar[e], off);
            an[e] += __shfl_xor_sync(0xffffffffu, an[e], off);
        }
    }
    if (lane == 0) {
        float ns[E_NUM];
        float best = -INFINITY; int bi = 0;
#pragma unroll
        for (int e = 0; e < E_NUM; e++) {
            float lg = ar[e] + b_route[e];
            float z  = an[e] + b_noise[e];
            float sp = fmaxf(z, 0.f) + log1pf(expf(-fabsf(z)));
            ns[e] = lg + noise[(size_t)t * E_NUM + e] * sp;
            if (ns[e] > best) { best = ns[e]; bi = e; }
        }
        float second = -INFINITY;
#pragma unroll
        for (int e = 0; e < E_NUM; e++)
            if (e != bi && ns[e] > second) second = ns[e];
        g_texp[t]  = bi;
        g_tgate[t] = 1.f / (1.f + expf(second - best));
    }
}

// ------------- ordered compaction (single block, 1024 thr, re-read) -------------
__global__ __launch_bounds__(1024) void kscatter() {
    __shared__ int s[E_NUM][1024];
    __shared__ int stot[E_NUM];
    const int tid = threadIdx.x;
    const int CH  = NTOK / 1024;   // 32
    const int t0  = tid * CH;

    int cnt[E_NUM];
#pragma unroll
    for (int e = 0; e < E_NUM; e++) cnt[e] = 0;
    for (int i = 0; i < CH; i++) cnt[g_texp[t0 + i]]++;
#pragma unroll
    for (int e = 0; e < E_NUM; e++) s[e][tid] = cnt[e];
    __syncthreads();
    for (int off = 1; off < 1024; off <<= 1) {
        int v[E_NUM];
#pragma unroll
        for (int e = 0; e < E_NUM; e++) v[e] = (tid >= off) ? s[e][tid - off] : 0;
        __syncthreads();
#pragma unroll
        for (int e = 0; e < E_NUM; e++) s[e][tid] += v[e];
        __syncthreads();
    }
    int run[E_NUM];
#pragma unroll
    for (int e = 0; e < E_NUM; e++) run[e] = s[e][tid] - cnt[e];
    if (tid < E_NUM) stot[tid] = s[tid][1023];
    __syncthreads();
    if (tid == 0) {
        int b = 0;
        for (int e = 0; e < E_NUM; e++) {
            int c = stot[e] < CAP ? stot[e] : CAP;
            g_count[e] = c;
            g_base[e]  = b;
            b += c;
        }
    }
    for (int i = 0; i < CH; i++) {
        int t = t0 + i;
        int e = g_texp[t];
        int p = run[e]++;
        if (p < CAP) {
            g_tok[e * CAP + p]   = t;
            g_gslot[e * CAP + p] = g_tgate[t];
        }
    }
}

// ========== ldmatrix fragment + mma block (one K-chunk, stage byte off ST) ==========
// warp tile: m = wm*64 + mt*16 (mt 0..3), n = wn*32 + j*8 (j 0..3)
#define FRAG_MMA_BLOCK(ST)                                                        \
    _Pragma("unroll")                                                             \
    for (int ks = 0; ks < 2; ks++) {                                              \
        uint32_t bh[8], bl[8];                                                    \
        LDSM_X4(bh[0], bh[1], bh[2], bh[3], bBaseH + (ST) + ks * 32);             \
        LDSM_X4(bh[4], bh[5], bh[6], bh[7], bBaseH + (ST) + 1280 + ks * 32);      \
        LDSM_X4(bl[0], bl[1], bl[2], bl[3], bBaseL + (ST) + ks * 32);             \
        LDSM_X4(bl[4], bl[5], bl[6], bl[7], bBaseL + (ST) + 1280 + ks * 32);      \
        _Pragma("unroll")                                                         \
        for (int mt = 0; mt < 4; mt++) {                                          \
            uint32_t ah[4], al[4];                                                \
            LDSM_X4(ah[0], ah[1], ah[2], ah[3],                                   \
                    aBaseH + (ST) + mt * (16 * RS * 2) + ks * 32);                \
            LDSM_X4(al[0], al[1], al[2], al[3],                                   \
                    aBaseL + (ST) + mt * (16 * RS * 2) + ks * 32);                \
            _Pragma("unroll")                                                     \
            for (int j = 0; j < 4; j++) {                                         \
                MMA_BF16(acc[mt][j], ah[0], ah[1], ah[2], ah[3],                  \
                         bh[2 * j], bh[2 * j + 1]);                               \
                MMA_BF16(acc[mt][j], al[0], al[1], al[2], al[3],                  \
                         bh[2 * j], bh[2 * j + 1]);                               \
                MMA_BF16(acc[mt][j], ah[0], ah[1], ah[2], ah[3],                  \
                         bl[2 * j], bl[2 * j + 1]);                               \
            }                                                                     \
        }                                                                         \
    }

#define SMEM_DECL extern __shared__ __align__(16) char dsm[];                     \
    const uint32_t sb = smem_to_u32(dsm);

#define FRAG_ADDR_DECL                                                            \
    const uint32_t aBaseH = sb + OFF_AH +                                         \
        (uint32_t)(((wm * 64 + (lane & 15)) * RS + (lane >> 4) * 8) * 2);         \
    const uint32_t aBaseL = sb + OFF_AL +                                         \
        (uint32_t)(((wm * 64 + (lane & 15)) * RS + (lane >> 4) * 8) * 2);         \
    const uint32_t bBaseH = sb + OFF_BH +                                         \
        (uint32_t)(((wn * 32 + (lane & 7) + ((lane >> 4) & 1) * 8) * RS +         \
                    ((lane >> 3) & 1) * 8) * 2);                                  \
    const uint32_t bBaseL = sb + OFF_BL +                                         \
        (uint32_t)(((wn * 32 + (lane & 7) + ((lane >> 4) & 1) * 8) * RS +         \
                    ((lane >> 3) & 1) * 8) * 2);

// per-thread staging map: assignments i = tid, tid+256; row = i>>2, 16B chunk = i&3
#define STAGE_IDX_DECL                                                            \
    const int rowS0 = tid >> 2,        chS0 = tid & 3;                            \
    const int rowS1 = (tid + 256) >> 2, chS1 = (tid + 256) & 3;                   \
    const uint32_t sOff0 = (uint32_t)(rowS0 * 80 + chS0 * 16);                    \
    const uint32_t sOff1 = (uint32_t)(rowS1 * 80 + chS1 * 16);

// ----------------- GEMM1: H = relu(Xg @ W1 + b1)^2 (bf16 split out) -----------------
__global__ __launch_bounds__(256, 2) void kgemm1_mma(const float* __restrict__ b1) {
    const int e   = blockIdx.z;
    const int cnt = g_count[e];
    const int m0  = blockIdx.y * TM;
    if (m0 >= cnt) return;
    const int n0  = blockIdx.x * TN;

    SMEM_DECL
    const int tid  = threadIdx.x;
    const int lane = tid & 31;
    const int wid  = tid >> 5;
    const int wm   = wid >> 2;          // 0..1
    const int wn   = wid & 3;           // 0..3
    const int fr   = lane >> 2;         // 0..7
    const int fc   = (lane & 3) * 2;    // 0,2,4,6
    FRAG_ADDR_DECL
    STAGE_IDX_DECL

    const int tk0 = g_tok[e * CAP + m0 + rowS0];
    const int tk1 = g_tok[e * CAP + m0 + rowS1];
    const size_t aG0 = (size_t)tk0 * C_DIM + chS0 * 8;
    const size_t aG1 = (size_t)tk1 * C_DIM + chS1 * 8;
    const size_t bG0 = (size_t)(e * DFF + n0 + rowS0) * C_DIM + chS0 * 8;
    const size_t bG1 = (size_t)(e * DFF + n0 + rowS1) * C_DIM + chS1 * 8;

    float acc[4][4][4];
#pragma unroll
    for (int a = 0; a < 4; a++)
#pragma unroll
        for (int b = 0; b < 4; b++)
#pragma unroll
            for (int c = 0; c < 4; c++) acc[a][b][c] = 0.f;

#define G1_ISSUE(K0, ST)                                                          \
    CP16(sb + OFF_AH + (ST) + sOff0, g_xhi + aG0 + (K0));                         \
    CP16(sb + OFF_AH + (ST) + sOff1, g_xhi + aG1 + (K0));                         \
    CP16(sb + OFF_AL + (ST) + sOff0, g_xlo + aG0 + (K0));                         \
    CP16(sb + OFF_AL + (ST) + sOff1, g_xlo + aG1 + (K0));                         \
    CP16(sb + OFF_BH + (ST) + sOff0, g_w1hi + bG0 + (K0));                        \
    CP16(sb + OFF_BH + (ST) + sOff1, g_w1hi + bG1 + (K0));                        \
    CP16(sb + OFF_BL + (ST) + sOff0, g_w1lo + bG0 + (K0));                        \
    CP16(sb + OFF_BL + (ST) + sOff1, g_w1lo + bG1 + (K0));                        \
    CP_COMMIT();

    G1_ISSUE(0, 0);
    const int NK = C_DIM / KC;   // 12
    for (int kci = 0; kci < NK; kci++) {
        CP_WAIT0();
        __syncthreads();
        const uint32_t st = (uint32_t)(kci & 1) * STG_B;
        if (kci + 1 < NK) { G1_ISSUE((kci + 1) * KC, st ^ STG_B); }
        FRAG_MMA_BLOCK(st);
    }
#undef G1_ISSUE

    // epilogue: bias + relu^2 + hi/lo split -> g_hhi/g_hlo
    const int gb = g_base[e];
    const int c0 = wn * 32 + fc;
    const float* b1p = b1 + (size_t)e * DFF + n0;
    float2 bj[4];
#pragma unroll
    for (int j = 0; j < 4; j++) bj[j] = *(const float2*)(b1p + c0 + j * 8);
#pragma unroll
    for (int mt = 0; mt < 4; mt++) {
#pragma unroll
        for (int hf = 0; hf < 2; hf++) {
            const int r = wm * 64 + mt * 16 + fr + hf * 8;
            const int p = m0 + r;
            if (p < cnt) {
                __nv_bfloat16* hh = g_hhi + (size_t)(gb + p) * DFF + n0;
                __nv_bfloat16* hl = g_hlo + (size_t)(gb + p) * DFF + n0;
#pragma unroll
                for (int j = 0; j < 4; j++) {
                    float v0 = acc[mt][j][hf * 2]     + bj[j].x;
                    float v1 = acc[mt][j][hf * 2 + 1] + bj[j].y;
                    v0 = fmaxf(v0, 0.f); v0 *= v0;
                    v1 = fmaxf(v1, 0.f); v1 *= v1;
                    __nv_bfloat16 h0 = __float2bfloat16(v0);
                    __nv_bfloat16 h1 = __float2bfloat16(v1);
                    __nv_bfloat16 l0 = __float2bfloat16(v0 - __bfloat162float(h0));
                    __nv_bfloat16 l1 = __float2bfloat16(v1 - __bfloat162float(h1));
                    *(__nv_bfloat162*)(hh + c0 + j * 8) = __nv_bfloat162(h0, h1);
                    *(__nv_bfloat162*)(hl + c0 + j * 8) = __nv_bfloat162(l0, l1);
                }
            }
        }
    }
}

// -------- GEMM2: out[tok] = gate * (H @ W2 + b2), scatter --------
__global__ __launch_bounds__(256, 2) void kgemm2_mma(const float* __restrict__ b2,
                                                     float* __restrict__ out) {
    const int e   = blockIdx.z;
    const int cnt = g_count[e];
    const int m0  = blockIdx.y * TM;
    if (m0 >= cnt) return;
    const int n0  = blockIdx.x * TN;

    SMEM_DECL
    const int tid  = threadIdx.x;
    const int lane = tid & 31;
    const int wid  = tid >> 5;
    const int wm   = wid >> 2;
    const int wn   = wid & 3;
    const int fr   = lane >> 2;
    const int fc   = (lane & 3) * 2;
    FRAG_ADDR_DECL
    STAGE_IDX_DECL

    const int gb = g_base[e];
    const size_t aG0 = (size_t)(gb + m0 + rowS0) * DFF + chS0 * 8;
    const size_t aG1 = (size_t)(gb + m0 + rowS1) * DFF + chS1 * 8;
    const size_t bG0 = (size_t)(e * C_DIM + n0 + rowS0) * DFF + chS0 * 8;
    const size_t bG1 = (size_t)(e * C_DIM + n0 + rowS1) * DFF + chS1 * 8;

    float acc[4][4][4];
#pragma unroll
    for (int a = 0; a < 4; a++)
#pragma unroll
        for (int b = 0; b < 4; b++)
#pragma unroll
            for (int c = 0; c < 4; c++) acc[a][b][c] = 0.f;

#define G2_ISSUE(K0, ST)                                                          \
    CP16(sb + OFF_AH + (ST) + sOff0, g_hhi + aG0 + (K0));                         \
    CP16(sb + OFF_AH + (ST) + sOff1, g_hhi + aG1 + (K0));                         \
    CP16(sb + OFF_AL + (ST) + sOff0, g_hlo + aG0 + (K0));                         \
    CP16(sb + OFF_AL + (ST) + sOff1, g_hlo + aG1 + (K0));                         \
    CP16(sb + OFF_BH + (ST) + sOff0, g_w2hi + bG0 + (K0));                        \
    CP16(sb + OFF_BH + (ST) + sOff1, g_w2hi + bG1 + (K0));                        \
    CP16(sb + OFF_BL + (ST) + sOff0, g_w2lo + bG0 + (K0));                        \
    CP16(sb + OFF_BL + (ST) + sOff1, g_w2lo + bG1 + (K0));                        \
    CP_COMMIT();

    G2_ISSUE(0, 0);
    const int NK = DFF / KC;   // 48
    for (int kci = 0; kci < NK; kci++) {
        CP_WAIT0();
        __syncthreads();
        const uint32_t st = (uint32_t)(kci & 1) * STG_B;
        if (kci + 1 < NK) { G2_ISSUE((kci + 1) * KC, st ^ STG_B); }
        FRAG_MMA_BLOCK(st);
    }
#undef G2_ISSUE

    const int c0 = wn * 32 + fc;
    const float* b2p = b2 + (size_t)e * C_DIM + n0;
    float2 bj[4];
#pragma unroll
    for (int j = 0; j < 4; j++) bj[j] = *(const float2*)(b2p + c0 + j * 8);
#pragma unroll
    for (int mt = 0; mt < 4; mt++) {
#pragma unroll
        for (int hf = 0; hf < 2; hf++) {
            const int r = wm * 64 + mt * 16 + fr + hf * 8;
            const int p = m0 + r;
            if (p < cnt) {
                const int tok  = g_tok[e * CAP + p];
                const float gt = g_gslot[e * CAP + p];
                float* op = out + (size_t)tok * C_DIM + n0 + c0;
#pragma unroll
                for (int j = 0; j < 4; j++) {
                    float2 v;
                    v.x = (acc[mt][j][hf * 2]     + bj[j].x) * gt;
                    v.y = (acc[mt][j][hf * 2 + 1] + bj[j].y) * gt;
                    *(float2*)(op + j * 8) = v;
                }
            }
        }
    }
}

// ---------------------------- launch ----------------------------
extern "C" void kernel_launch(void* const* d_in, const int* in_sizes, int n_in,
                              void* d_out, int out_size) {
    const float* x       = (const float*)d_in[0];
    const float* noise   = (const float*)d_in[1];
    const float* w_route = (const float*)d_in[2];
    const float* b_route = (const float*)d_in[3];
    const float* w_noise = (const float*)d_in[4];
    const float* b_noise = (const float*)d_in[5];
    const float* w1      = (const float*)d_in[6];
    const float* b1      = (const float*)d_in[7];
    const float* w2      = (const float*)d_in[8];
    const float* b2      = (const float*)d_in[9];
    float* out = (float*)d_out;

    cudaFuncSetAttribute(kgemm1_mma, cudaFuncAttributeMaxDynamicSharedMemorySize, SMEM_TOT);
    cudaFuncSetAttribute(kgemm2_mma, cudaFuncAttributeMaxDynamicSharedMemorySize, SMEM_TOT);

    kconv_x<<<NTOK * C_DIM / 2 / 256, 256>>>((const float2*)x, (float2*)out);
    ktrans<<<dim3(DFF / 32, C_DIM / 32, E_NUM), dim3(32, 8)>>>(w1, 0, C_DIM, DFF);
    ktrans<<<dim3(C_DIM / 32, DFF / 32, E_NUM), dim3(32, 8)>>>(w2, 1, DFF, C_DIM);
    kroute<<<NTOK / 8, 256>>>(x, noise, w_route, b_route, w_noise, b_noise);
    kscatter<<<1, 1024>>>();
    kgemm1_mma<<<dim3(DFF / TN, CAP / TM, E_NUM), 256, SMEM_TOT>>>(b1);
    kgemm2_mma<<<dim3(C_DIM / TN, CAP / TM, E_NUM), 256, SMEM_TOT>>>(b2, out);
}